// round 1
// baseline (speedup 1.0000x reference)
#include <cuda_runtime.h>
#include <cstddef>

// Problem constants
#define NB   8
#define CC   512
#define WW   8192
#define HH   8
#define HD   64

// Scratch (device globals — allocation-free per harness rules)
__device__ float g_keys[(size_t)NB * CC * WW];   // 128 MB
__device__ float g_quer[(size_t)NB * CC * WW];   // 128 MB (softQ written in place)
__device__ float g_vals[(size_t)NB * CC * WW];   // 128 MB
__device__ float g_rowm[NB * CC];
__device__ float g_rows[NB * CC];
__device__ float g_ctxp[64 * 8 * HD * HD];       // partial ctx per (n*h, wchunk)
__device__ float g_ctx[64 * HD * HD];            // normalized ctx
__device__ float g_M[(size_t)NB * CC * CC];      // folded Wr @ ctx^T / s

// ---------------------------------------------------------------------------
// Generic 128x128x(K=512) fp32 SGEMM body. A row-major [512x512] (rowbase
// selects 128-row slab), B row-major [512x8192]. Bias per row; optional
// residual added in epilogue.
// ---------------------------------------------------------------------------
__device__ __forceinline__ void sgemm_body(
    const float* __restrict__ A, int rowbase,
    const float* __restrict__ B,
    const float* __restrict__ bias,
    const float* __restrict__ resid,
    float* __restrict__ O)
{
    __shared__ float As[16][128];
    __shared__ float Bs[16][128];
    const int t = threadIdx.x;
    const int colbase = blockIdx.x * 128;
    const int tm = (t >> 4) << 3;   // 0..120
    const int tn = (t & 15) << 3;   // 0..120
    float acc[8][8] = {};

    for (int k0 = 0; k0 < 512; k0 += 16) {
#pragma unroll
        for (int u = 0; u < 2; ++u) {
            int id = t + u * 256;
            // A tile: 128 rows x 16 cols, stored transposed
            int ra = id >> 2;
            int ca = (id & 3) << 2;
            float4 va = *(const float4*)(A + (size_t)(rowbase + ra) * 512 + k0 + ca);
            As[ca + 0][ra] = va.x;
            As[ca + 1][ra] = va.y;
            As[ca + 2][ra] = va.z;
            As[ca + 3][ra] = va.w;
            // B tile: 16 rows x 128 cols
            int rb = id >> 5;
            int cb = (id & 31) << 2;
            *(float4*)&Bs[rb][cb] =
                *(const float4*)(B + (size_t)(k0 + rb) * WW + colbase + cb);
        }
        __syncthreads();
#pragma unroll
        for (int kk = 0; kk < 16; ++kk) {
            float a_[8], b_[8];
            *(float4*)&a_[0] = *(float4*)&As[kk][tm];
            *(float4*)&a_[4] = *(float4*)&As[kk][tm + 4];
            *(float4*)&b_[0] = *(float4*)&Bs[kk][tn];
            *(float4*)&b_[4] = *(float4*)&Bs[kk][tn + 4];
#pragma unroll
            for (int i = 0; i < 8; ++i)
#pragma unroll
                for (int j = 0; j < 8; ++j)
                    acc[i][j] = fmaf(a_[i], b_[j], acc[i][j]);
        }
        __syncthreads();
    }

#pragma unroll
    for (int i = 0; i < 8; ++i) {
        int r = rowbase + tm + i;
        float bi = bias[r];
        float* orow = O + (size_t)r * WW + colbase + tn;
        const float* rrow = resid ? resid + (size_t)r * WW + colbase + tn : nullptr;
#pragma unroll
        for (int j4 = 0; j4 < 8; j4 += 4) {
            float4 v;
            v.x = acc[i][j4 + 0] + bi;
            v.y = acc[i][j4 + 1] + bi;
            v.z = acc[i][j4 + 2] + bi;
            v.w = acc[i][j4 + 3] + bi;
            if (rrow) {
                float4 rv = *(const float4*)(rrow + j4);
                v.x += rv.x; v.y += rv.y; v.z += rv.z; v.w += rv.w;
            }
            *(float4*)(orow + j4) = v;
        }
    }
}

// ---------------------------------------------------------------------------
// Kernel 1: fused K/Q/V projections. grid = (64 wtiles, 12 rowtiles, 8 batch)
// ---------------------------------------------------------------------------
__global__ void __launch_bounds__(256)
k_proj(const float* __restrict__ x,
       const float* __restrict__ Wk, const float* __restrict__ bk,
       const float* __restrict__ Wq, const float* __restrict__ bq,
       const float* __restrict__ Wv, const float* __restrict__ bv)
{
    int sect = blockIdx.y >> 2;            // 0=K 1=Q 2=V
    int rowbase = (blockIdx.y & 3) * 128;  // within section
    int n = blockIdx.z;
    const float* A;
    const float* bias;
    float* O;
    if (sect == 0)      { A = Wk; bias = bk; O = g_keys; }
    else if (sect == 1) { A = Wq; bias = bq; O = g_quer; }
    else                { A = Wv; bias = bv; O = g_vals; }
    const float* B = x + (size_t)n * CC * WW;
    O += (size_t)n * CC * WW;
    sgemm_body(A, rowbase, B, bias, nullptr, O);
}

// ---------------------------------------------------------------------------
// Kernel 2: per-row max + sum(exp) for keys. One block per row.
// ---------------------------------------------------------------------------
__global__ void __launch_bounds__(256) k_rowstats()
{
    int row = blockIdx.x;  // 0..4095
    const float* p = g_keys + (size_t)row * WW;
    int t = threadIdx.x;
    __shared__ float red[256];

    float m = -1e30f;
    for (int i = t; i < WW; i += 256) m = fmaxf(m, p[i]);
    red[t] = m;
    __syncthreads();
    for (int s = 128; s > 0; s >>= 1) {
        if (t < s) red[t] = fmaxf(red[t], red[t + s]);
        __syncthreads();
    }
    m = red[0];
    __syncthreads();

    float s = 0.f;
    for (int i = t; i < WW; i += 256) s += __expf(p[i] - m);
    red[t] = s;
    __syncthreads();
    for (int s2 = 128; s2 > 0; s2 >>= 1) {
        if (t < s2) red[t] += red[t + s2];
        __syncthreads();
    }
    if (t == 0) { g_rowm[row] = m; g_rows[row] = red[0]; }
}

// ---------------------------------------------------------------------------
// Kernel 3: partial ctx = exp(keys - m) @ V^T over a 1024-wide w chunk.
// grid = (64 nh, 8 chunks), 256 threads, 4x4 microtile of the 64x64 output.
// ---------------------------------------------------------------------------
__global__ void __launch_bounds__(256) k_ctx()
{
    int nh = blockIdx.x;
    int chunk = blockIdx.y;
    int t = threadIdx.x;
    __shared__ float eK[64][33];
    __shared__ float Vs[64][33];

    int rowbase = nh * 64;
    int wbase = chunk * 1024;
    int lr = t >> 2;          // 0..63 load row
    int lc = (t & 3) << 3;    // 0,8,16,24
    float m = g_rowm[rowbase + lr];
    const float* kp = g_keys + (size_t)(rowbase + lr) * WW + wbase + lc;
    const float* vp = g_vals + (size_t)(rowbase + lr) * WW + wbase + lc;

    int k0 = (t >> 4) << 2;   // 0..60
    int v0 = (t & 15) << 2;   // 0..60
    float acc[4][4] = {};

    for (int c = 0; c < 32; ++c) {
        __syncthreads();
#pragma unroll
        for (int i = 0; i < 8; ++i) {
            eK[lr][lc + i] = __expf(kp[c * 32 + i] - m);
            Vs[lr][lc + i] = vp[c * 32 + i];
        }
        __syncthreads();
#pragma unroll
        for (int tt = 0; tt < 32; ++tt) {
            float a_[4], b_[4];
#pragma unroll
            for (int i = 0; i < 4; ++i) a_[i] = eK[k0 + i][tt];
#pragma unroll
            for (int j = 0; j < 4; ++j) b_[j] = Vs[v0 + j][tt];
#pragma unroll
            for (int i = 0; i < 4; ++i)
#pragma unroll
                for (int j = 0; j < 4; ++j)
                    acc[i][j] = fmaf(a_[i], b_[j], acc[i][j]);
        }
    }
    float* op = g_ctxp + (size_t)(nh * 8 + chunk) * 4096;
#pragma unroll
    for (int i = 0; i < 4; ++i)
#pragma unroll
        for (int j = 0; j < 4; ++j)
            op[(k0 + i) * 64 + v0 + j] = acc[i][j];
}

// ---------------------------------------------------------------------------
// Kernel 4: reduce ctx partials across 8 chunks and fold in 1/rowsum.
// ---------------------------------------------------------------------------
__global__ void __launch_bounds__(256) k_reduce()
{
    int nh = blockIdx.x;
    int t = threadIdx.x;
    for (int e = t; e < 4096; e += 256) {
        float sum = 0.f;
#pragma unroll
        for (int c = 0; c < 8; ++c) sum += g_ctxp[(size_t)(nh * 8 + c) * 4096 + e];
        int k = e >> 6;
        g_ctx[(size_t)nh * 4096 + e] = sum / g_rows[nh * 64 + k];
    }
}

// ---------------------------------------------------------------------------
// Kernel 5: M[n][c][h*64+k] = sum_v Wr[c][h*64+v] * ctx[n][h][k][v]
// grid = (8 ctiles, 8 heads, 8 batch)
// ---------------------------------------------------------------------------
__global__ void __launch_bounds__(256) k_M(const float* __restrict__ Wr)
{
    int ct = blockIdx.x, h = blockIdx.y, n = blockIdx.z;
    __shared__ float Ws[64][65];
    __shared__ float Cs[64][65];
    int t = threadIdx.x;

    for (int e = t; e < 4096; e += 256) {
        int r = e >> 6, c = e & 63;
        Ws[r][c] = Wr[(size_t)(ct * 64 + r) * 512 + h * 64 + c];
        Cs[r][c] = g_ctx[(size_t)(n * 8 + h) * 4096 + e];
    }
    __syncthreads();

    int c0 = (t >> 4) << 2;
    int k0 = (t & 15) << 2;
    float acc[4][4] = {};
    for (int v = 0; v < 64; ++v) {
        float a_[4], b_[4];
#pragma unroll
        for (int i = 0; i < 4; ++i) a_[i] = Ws[c0 + i][v];
#pragma unroll
        for (int j = 0; j < 4; ++j) b_[j] = Cs[k0 + j][v];
#pragma unroll
        for (int i = 0; i < 4; ++i)
#pragma unroll
            for (int j = 0; j < 4; ++j)
                acc[i][j] = fmaf(a_[i], b_[j], acc[i][j]);
    }
#pragma unroll
    for (int i = 0; i < 4; ++i)
#pragma unroll
        for (int j = 0; j < 4; ++j)
            g_M[(size_t)n * 262144 + (size_t)(ct * 64 + c0 + i) * 512 + h * 64 + k0 + j]
                = acc[i][j];
}

// ---------------------------------------------------------------------------
// Kernel 6: column softmax of queries over the 64 channels of each head,
// written in place. One thread per (n, h, w) column; online max/sum pass,
// then normalize pass.
// ---------------------------------------------------------------------------
__global__ void __launch_bounds__(256) k_softq()
{
    int cid = blockIdx.x * 256 + threadIdx.x;  // 0 .. 524287
    int n = cid >> 16;
    int rem = cid & 65535;
    int h = rem >> 13;
    int w = rem & 8191;
    float* base = g_quer + ((size_t)(n * 512 + h * 64)) * WW + w;

    float m = -1e30f, s = 0.f;
#pragma unroll 4
    for (int k = 0; k < 64; ++k) {
        float v = base[(size_t)k * WW];
        float mn = fmaxf(m, v);
        s = s * __expf(m - mn) + __expf(v - mn);
        m = mn;
    }
    float inv = 1.0f / s;
#pragma unroll 4
    for (int k = 0; k < 64; ++k) {
        float v = base[(size_t)k * WW];
        base[(size_t)k * WW] = __expf(v - m) * inv;
    }
}

// ---------------------------------------------------------------------------
// Kernel 7: out = x + br + M @ softQ.  grid = (64 wtiles, 4 rowtiles, 8 batch)
// ---------------------------------------------------------------------------
__global__ void __launch_bounds__(256)
k_out(const float* __restrict__ x, const float* __restrict__ br,
      float* __restrict__ out)
{
    int rowbase = blockIdx.y * 128;
    int n = blockIdx.z;
    const float* A = g_M + (size_t)n * 262144;
    const float* B = g_quer + (size_t)n * CC * WW;
    const float* resid = x + (size_t)n * CC * WW;
    float* O = out + (size_t)n * CC * WW;
    sgemm_body(A, rowbase, B, br, resid, O);
}

// ---------------------------------------------------------------------------
extern "C" void kernel_launch(void* const* d_in, const int* in_sizes, int n_in,
                              void* d_out, int out_size)
{
    const float* x  = (const float*)d_in[0];
    const float* Wk = (const float*)d_in[1];
    const float* bk = (const float*)d_in[2];
    const float* Wq = (const float*)d_in[3];
    const float* bq = (const float*)d_in[4];
    const float* Wv = (const float*)d_in[5];
    const float* bv = (const float*)d_in[6];
    const float* Wr = (const float*)d_in[7];
    const float* br = (const float*)d_in[8];
    float* out = (float*)d_out;

    k_proj<<<dim3(64, 12, 8), 256>>>(x, Wk, bk, Wq, bq, Wv, bv);
    k_rowstats<<<4096, 256>>>();
    k_ctx<<<dim3(64, 8), 256>>>();
    k_reduce<<<64, 256>>>();
    k_M<<<dim3(8, 8, 8), 256>>>(Wr);
    k_softq<<<2048, 256>>>();
    k_out<<<dim3(64, 4, 8), 256>>>(x, br, out);
}

// round 3
// speedup vs baseline: 3.7161x; 3.7161x over previous
#include <cuda_runtime.h>
#include <cuda_bf16.h>
#include <cstdint>
#include <cstddef>

#define NB 8
#define CC 512
#define WW 8192
#define HH 8

typedef __nv_bfloat16 bf16;

// ---------------- scratch (device globals; allocation-free) ----------------
__device__ bf16  g_xt  [(size_t)NB * WW * CC];   // x transposed [n][w][c] bf16
__device__ bf16  g_wb  [3 * CC * CC];            // Wk,Wq,Wv bf16
__device__ bf16  g_keysb[(size_t)NB * CC * WW];  // keys [n][c][w] bf16
__device__ bf16  g_querb[(size_t)NB * CC * WW];  // queries
__device__ bf16  g_valsb[(size_t)NB * CC * WW];  // values
__device__ bf16  g_sqt [(size_t)NB * WW * CC];   // softmax(Q) transposed [n][w][c]
__device__ bf16  g_Mb  [(size_t)NB * CC * CC];   // folded Wr@ctx^T (bf16)
__device__ float g_rows[NB * CC];                // sum(exp(keys)) per row
__device__ float g_ctxp[64 * 8 * 64 * 64];       // ctx partials
__device__ float g_ctx [64 * 64 * 64];           // normalized ctx

// ---------------- helpers (arch-neutral: ldmatrix / mma.sync / cp.async) ----
__device__ __forceinline__ uint32_t smem_u32(const void* p) {
    uint32_t a;
    asm("{ .reg .u64 t; cvta.to.shared.u64 t, %1; cvt.u32.u64 %0, t; }"
        : "=r"(a) : "l"(p));
    return a;
}
__device__ __forceinline__ void ldmx4(uint32_t* r, uint32_t addr) {
    asm volatile("ldmatrix.sync.aligned.m8n8.x4.shared.b16 {%0,%1,%2,%3}, [%4];"
                 : "=r"(r[0]), "=r"(r[1]), "=r"(r[2]), "=r"(r[3]) : "r"(addr));
}
__device__ __forceinline__ void mma_bf16(float* c, const uint32_t* a,
                                         const uint32_t b0, const uint32_t b1) {
    asm volatile(
        "mma.sync.aligned.m16n8k16.row.col.f32.bf16.bf16.f32 "
        "{%0,%1,%2,%3}, {%4,%5,%6,%7}, {%8,%9}, {%0,%1,%2,%3};"
        : "+f"(c[0]), "+f"(c[1]), "+f"(c[2]), "+f"(c[3])
        : "r"(a[0]), "r"(a[1]), "r"(a[2]), "r"(a[3]), "r"(b0), "r"(b1));
}
__device__ __forceinline__ void cp16(uint32_t dst, const void* src) {
    asm volatile("cp.async.cg.shared.global [%0], [%1], 16;" :: "r"(dst), "l"(src));
}
__device__ __forceinline__ void cp_commit() {
    asm volatile("cp.async.commit_group;");
}
template <int N>
__device__ __forceinline__ void cp_wait() {
    asm volatile("cp.async.wait_group %0;" :: "n"(N));
}

// ---------------------------------------------------------------------------
// HMMA GEMM body: D[128 x 128] = A[128 x 512] * B[colbase..+128, 512]^T
// A, B bf16 K-major row-major. Double-buffered cp.async, BK=32.
// ---------------------------------------------------------------------------
#define BK 32
#define STRD 40   // smem row stride in elements (80 B; conflict-free ldmatrix)

__device__ __forceinline__ void mm_body(
    const bf16* __restrict__ A,          // pre-offset to its 128-row slab
    const bf16* __restrict__ B,          // [8192 x 512] per-batch slab
    const float* __restrict__ bias,      // pre-offset [128]
    const float* __restrict__ resid,     // pre-offset rows (or nullptr)
    void* __restrict__ outp,             // pre-offset rows
    bool bf16out)
{
    __shared__ __align__(16) bf16 As[2][128 * STRD];
    __shared__ __align__(16) bf16 Bs[2][128 * STRD];

    const int tid = threadIdx.x;
    const int lane = tid & 31;
    const int wid = tid >> 5;
    const int wm = (wid & 1) * 64;    // warp M base
    const int wn = (wid >> 1) * 32;   // warp N base
    const int colbase = blockIdx.x * 128;

    const uint32_t sA[2] = { smem_u32(As[0]), smem_u32(As[1]) };
    const uint32_t sB[2] = { smem_u32(Bs[0]), smem_u32(Bs[1]) };

    // gmem load coords for this thread (2 x 16B per tile per array)
    const int r0 = tid >> 2;                 // 0..63
    const int c8 = (tid & 3) << 3;           // 0,8,16,24

    float acc[4][4][4] = {};

    // prologue: stage 0
    {
#pragma unroll
        for (int u = 0; u < 2; ++u) {
            int row = r0 + u * 64;
            uint32_t so = (uint32_t)(row * STRD + c8) * 2;
            cp16(sA[0] + so, A + (size_t)row * 512 + c8);
            cp16(sB[0] + so, B + (size_t)(colbase + row) * 512 + c8);
        }
        cp_commit();
    }

    for (int ch = 0; ch < 16; ++ch) {
        const int cur = ch & 1;
        if (ch < 15) {
            const int k0 = (ch + 1) * BK;
#pragma unroll
            for (int u = 0; u < 2; ++u) {
                int row = r0 + u * 64;
                uint32_t so = (uint32_t)(row * STRD + c8) * 2;
                cp16(sA[cur ^ 1] + so, A + (size_t)row * 512 + k0 + c8);
                cp16(sB[cur ^ 1] + so, B + (size_t)(colbase + row) * 512 + k0 + c8);
            }
            cp_commit();
            cp_wait<1>();
        } else {
            cp_wait<0>();
        }
        __syncthreads();

#pragma unroll
        for (int ks = 0; ks < 2; ++ks) {
            uint32_t a[4][4], b[2][4];
            const int kA = ks * 16 + ((lane >> 4) << 3);
            const int kB = ks * 16 + (((lane >> 3) & 1) << 3);
#pragma unroll
            for (int i = 0; i < 4; ++i)
                ldmx4(a[i], sA[cur] +
                      (uint32_t)((wm + i * 16 + (lane & 15)) * STRD + kA) * 2);
#pragma unroll
            for (int j2 = 0; j2 < 2; ++j2)
                ldmx4(b[j2], sB[cur] +
                      (uint32_t)((wn + j2 * 16 + (lane & 7) + ((lane >> 4) << 3))
                                 * STRD + kB) * 2);
#pragma unroll
            for (int i = 0; i < 4; ++i)
#pragma unroll
                for (int j = 0; j < 4; ++j)
                    mma_bf16(acc[i][j], a[i], b[j >> 1][(j & 1) * 2],
                             b[j >> 1][(j & 1) * 2 + 1]);
        }
        __syncthreads();
    }

    // epilogue: C frag layout c0,c1 -> [m=lane/4][n=2*(lane%4)+0,1]; c2,c3 -> m+8
    const int mrow = wm + (lane >> 2);
    const int ncol = colbase + wn + 2 * (lane & 3);
#pragma unroll
    for (int i = 0; i < 4; ++i) {
        int m0 = mrow + i * 16;
        float b0 = bias[m0], b1 = bias[m0 + 8];
#pragma unroll
        for (int j = 0; j < 4; ++j) {
            int n = ncol + j * 8;
            float* c = acc[i][j];
            if (bf16out) {
                bf16* o = (bf16*)outp;
                *(__nv_bfloat162*)(o + (size_t)m0 * WW + n) =
                    __floats2bfloat162_rn(c[0] + b0, c[1] + b0);
                *(__nv_bfloat162*)(o + (size_t)(m0 + 8) * WW + n) =
                    __floats2bfloat162_rn(c[2] + b1, c[3] + b1);
            } else {
                float* o = (float*)outp;
                const float* rr = resid;
                float2 r0v = *(const float2*)(rr + (size_t)m0 * WW + n);
                float2 r1v = *(const float2*)(rr + (size_t)(m0 + 8) * WW + n);
                float2 o0 = { c[0] + b0 + r0v.x, c[1] + b0 + r0v.y };
                float2 o1 = { c[2] + b1 + r1v.x, c[3] + b1 + r1v.y };
                *(float2*)(o + (size_t)m0 * WW + n) = o0;
                *(float2*)(o + (size_t)(m0 + 8) * WW + n) = o1;
            }
        }
    }
}

// ---------------------------------------------------------------------------
// conversions
// ---------------------------------------------------------------------------
__global__ void __launch_bounds__(256)
k_convw(const float* __restrict__ s, bf16* __restrict__ d)
{
    int i = (blockIdx.x * 256 + threadIdx.x) * 4;
    float4 v = *(const float4*)(s + i);
    __nv_bfloat162 o[2];
    o[0] = __floats2bfloat162_rn(v.x, v.y);
    o[1] = __floats2bfloat162_rn(v.z, v.w);
    *(uint2*)(d + i) = *(uint2*)o;
}

__global__ void __launch_bounds__(256)
k_convx(const float* __restrict__ x)
{
    __shared__ float tile[32][33];
    int n = blockIdx.z, c0 = blockIdx.y * 32, w0 = blockIdx.x * 32;
    int tx = threadIdx.x, ty = threadIdx.y;
    const float* xb = x + (size_t)n * CC * WW;
#pragma unroll
    for (int i = ty; i < 32; i += 8)
        tile[i][tx] = xb[(size_t)(c0 + i) * WW + w0 + tx];
    __syncthreads();
    bf16* ob = g_xt + (size_t)n * WW * CC;
#pragma unroll
    for (int i = ty; i < 32; i += 8)
        ob[(size_t)(w0 + i) * CC + c0 + tx] = __float2bfloat16(tile[tx][i]);
}

// ---------------------------------------------------------------------------
// GEMM wrappers
// ---------------------------------------------------------------------------
__global__ void __launch_bounds__(256)
k_proj(const float* __restrict__ bk, const float* __restrict__ bq,
       const float* __restrict__ bv)
{
    int mtile = blockIdx.y;
    int sect = mtile >> 2;
    int mbrow = (mtile & 3) * 128;
    int n = blockIdx.z;
    const bf16* A = g_wb + (size_t)sect * CC * CC + (size_t)mbrow * CC;
    const bf16* B = g_xt + (size_t)n * WW * CC;
    const float* bias = (sect == 0 ? bk : sect == 1 ? bq : bv) + mbrow;
    bf16* out = (sect == 0 ? g_keysb : sect == 1 ? g_querb : g_valsb)
                + (size_t)n * CC * WW + (size_t)mbrow * WW;
    mm_body(A, B, bias, nullptr, out, true);
}

__global__ void __launch_bounds__(256)
k_out(const float* __restrict__ x, const float* __restrict__ br,
      float* __restrict__ out)
{
    int mbrow = blockIdx.y * 128;
    int n = blockIdx.z;
    const bf16* A = g_Mb + (size_t)n * CC * CC + (size_t)mbrow * CC;
    const bf16* B = g_sqt + (size_t)n * WW * CC;
    const float* resid = x + (size_t)n * CC * WW + (size_t)mbrow * WW;
    float* O = out + (size_t)n * CC * WW + (size_t)mbrow * WW;
    mm_body(A, B, br + mbrow, resid, O, false);
}

// ---------------------------------------------------------------------------
// key row sums: sum(exp(keys)) per (n, kc) row — no max pass (|keys| small)
// ---------------------------------------------------------------------------
__global__ void __launch_bounds__(256) k_rowsum()
{
    int row = blockIdx.x;
    int t = threadIdx.x;
    const __nv_bfloat162* p = (const __nv_bfloat162*)(g_keysb + (size_t)row * WW);
    float s = 0.f;
    for (int i = t; i < WW / 2; i += 256) {
        float2 f = __bfloat1622float2(p[i]);
        s += __expf(f.x) + __expf(f.y);
    }
    __shared__ float red[256];
    red[t] = s;
    __syncthreads();
    for (int k = 128; k > 0; k >>= 1) {
        if (t < k) red[t] += red[t + k];
        __syncthreads();
    }
    if (t == 0) g_rows[row] = red[0];
}

// ---------------------------------------------------------------------------
// ctx partials: exp(keys) @ V^T over 1024-wide w chunks
// ---------------------------------------------------------------------------
__global__ void __launch_bounds__(256) k_ctx()
{
    int nh = blockIdx.x, chunk = blockIdx.y, t = threadIdx.x;
    __shared__ float eK[64][33];
    __shared__ float Vs[64][33];

    int rowbase = nh * 64;
    int wbase = chunk * 1024;
    int lr = t >> 2;
    int lc = (t & 3) << 3;
    const uint4* kq = (const uint4*)(g_keysb + (size_t)(rowbase + lr) * WW + wbase + lc);
    const uint4* vq = (const uint4*)(g_valsb + (size_t)(rowbase + lr) * WW + wbase + lc);

    int k0 = (t >> 4) << 2;
    int v0 = (t & 15) << 2;
    float acc[4][4] = {};

    for (int c = 0; c < 32; ++c) {
        __syncthreads();
        uint4 kd = kq[c * 4];
        uint4 vd = vq[c * 4];
        const __nv_bfloat162* kh = (const __nv_bfloat162*)&kd;
        const __nv_bfloat162* vh = (const __nv_bfloat162*)&vd;
#pragma unroll
        for (int i = 0; i < 4; ++i) {
            float2 kf = __bfloat1622float2(kh[i]);
            float2 vf = __bfloat1622float2(vh[i]);
            eK[lr][lc + 2 * i + 0] = __expf(kf.x);
            eK[lr][lc + 2 * i + 1] = __expf(kf.y);
            Vs[lr][lc + 2 * i + 0] = vf.x;
            Vs[lr][lc + 2 * i + 1] = vf.y;
        }
        __syncthreads();
#pragma unroll
        for (int tt = 0; tt < 32; ++tt) {
            float a_[4], b_[4];
#pragma unroll
            for (int i = 0; i < 4; ++i) a_[i] = eK[k0 + i][tt];
#pragma unroll
            for (int j = 0; j < 4; ++j) b_[j] = Vs[v0 + j][tt];
#pragma unroll
            for (int i = 0; i < 4; ++i)
#pragma unroll
                for (int j = 0; j < 4; ++j)
                    acc[i][j] = fmaf(a_[i], b_[j], acc[i][j]);
        }
    }
    float* op = g_ctxp + (size_t)(nh * 8 + chunk) * 4096;
#pragma unroll
    for (int i = 0; i < 4; ++i)
#pragma unroll
        for (int j = 0; j < 4; ++j)
            op[(k0 + i) * 64 + v0 + j] = acc[i][j];
}

__global__ void __launch_bounds__(256) k_reduce()
{
    int nh = blockIdx.x, t = threadIdx.x;
    for (int e = t; e < 4096; e += 256) {
        float sum = 0.f;
#pragma unroll
        for (int c = 0; c < 8; ++c) sum += g_ctxp[(size_t)(nh * 8 + c) * 4096 + e];
        int k = e >> 6;
        g_ctx[(size_t)nh * 4096 + e] = sum / g_rows[nh * 64 + k];
    }
}

// ---------------------------------------------------------------------------
// M[n][c][h*64+k] = sum_v Wr[c][h*64+v] * ctx[n][h][k][v]  (bf16 out)
// ---------------------------------------------------------------------------
__global__ void __launch_bounds__(256) k_M(const float* __restrict__ Wr)
{
    int ct = blockIdx.x, h = blockIdx.y, n = blockIdx.z;
    __shared__ float Ws[64][65];
    __shared__ float Cs[64][65];
    int t = threadIdx.x;

    for (int e = t; e < 4096; e += 256) {
        int r = e >> 6, c = e & 63;
        Ws[r][c] = Wr[(size_t)(ct * 64 + r) * 512 + h * 64 + c];
        Cs[r][c] = g_ctx[(size_t)(n * 8 + h) * 4096 + e];
    }
    __syncthreads();

    int c0 = (t >> 4) << 2;
    int k0 = (t & 15) << 2;
    float acc[4][4] = {};
    for (int v = 0; v < 64; ++v) {
        float a_[4], b_[4];
#pragma unroll
        for (int i = 0; i < 4; ++i) a_[i] = Ws[c0 + i][v];
#pragma unroll
        for (int j = 0; j < 4; ++j) b_[j] = Cs[k0 + j][v];
#pragma unroll
        for (int i = 0; i < 4; ++i)
#pragma unroll
            for (int j = 0; j < 4; ++j)
                acc[i][j] = fmaf(a_[i], b_[j], acc[i][j]);
    }
#pragma unroll
    for (int i = 0; i < 4; ++i)
#pragma unroll
        for (int j = 0; j < 4; ++j)
            g_Mb[(size_t)n * 262144 + (size_t)(ct * 64 + c0 + i) * 512 + h * 64 + k0 + j]
                = __float2bfloat16(acc[i][j]);
}

// ---------------------------------------------------------------------------
// column softmax of queries (over 64 channels per head), output transposed
// ---------------------------------------------------------------------------
__global__ void __launch_bounds__(256) k_softq()
{
    int cid = blockIdx.x * 256 + threadIdx.x;  // 0 .. 524287
    int n = cid >> 16;
    int h = (cid >> 13) & 7;
    int w = cid & 8191;
    const bf16* base = g_querb + ((size_t)(n * CC + h * 64)) * WW + w;

    float v[64];
#pragma unroll
    for (int k = 0; k < 64; ++k) v[k] = __bfloat162float(base[(size_t)k * WW]);
    float m = v[0];
#pragma unroll
    for (int k = 1; k < 64; ++k) m = fmaxf(m, v[k]);
    float s = 0.f;
#pragma unroll
    for (int k = 0; k < 64; ++k) { v[k] = __expf(v[k] - m); s += v[k]; }
    float inv = 1.0f / s;
    __nv_bfloat162 o[32];
#pragma unroll
    for (int k = 0; k < 32; ++k)
        o[k] = __floats2bfloat162_rn(v[2 * k] * inv, v[2 * k + 1] * inv);
    uint4* dst = (uint4*)(g_sqt + ((size_t)n * WW + w) * CC + h * 64);
#pragma unroll
    for (int q = 0; q < 8; ++q) dst[q] = ((uint4*)o)[q];
}

// ---------------------------------------------------------------------------
extern "C" void kernel_launch(void* const* d_in, const int* in_sizes, int n_in,
                              void* d_out, int out_size)
{
    const float* x  = (const float*)d_in[0];
    const float* Wk = (const float*)d_in[1];
    const float* bk = (const float*)d_in[2];
    const float* Wq = (const float*)d_in[3];
    const float* bq = (const float*)d_in[4];
    const float* Wv = (const float*)d_in[5];
    const float* bv = (const float*)d_in[6];
    const float* Wr = (const float*)d_in[7];
    const float* br = (const float*)d_in[8];
    float* out = (float*)d_out;

    bf16* wb;
    cudaGetSymbolAddress((void**)&wb, g_wb);

    k_convw<<<256, 256>>>(Wk, wb);
    k_convw<<<256, 256>>>(Wq, wb + 262144);
    k_convw<<<256, 256>>>(Wv, wb + 524288);
    k_convx<<<dim3(256, 16, 8), dim3(32, 8)>>>(x);
    k_proj<<<dim3(64, 12, 8), 256>>>(bk, bq, bv);
    k_rowsum<<<4096, 256>>>();
    k_ctx<<<dim3(64, 8), 256>>>();
    k_reduce<<<64, 256>>>();
    k_M<<<dim3(8, 8, 8), 256>>>(Wr);
    k_softq<<<2048, 256>>>();
    k_out<<<dim3(64, 4, 8), 256>>>(x, br, out);
}

// round 5
// speedup vs baseline: 4.2084x; 1.1325x over previous
#include <cuda_runtime.h>
#include <cuda_bf16.h>
#include <cstdint>
#include <cstddef>

#define NB 8
#define CC 512
#define WW 8192
#define HH 8

typedef __nv_bfloat16 bf16;

// ---------------- scratch (device globals; allocation-free) ----------------
__device__ bf16  g_xt  [(size_t)NB * WW * CC];   // x transposed [n][w][c] bf16
__device__ bf16  g_wb  [3 * CC * CC];            // Wk,Wq,Wv bf16
__device__ bf16  g_keysb[(size_t)NB * CC * WW];  // keys [n][c][w] bf16
__device__ bf16  g_querb[(size_t)NB * CC * WW];  // queries
__device__ bf16  g_valsb[(size_t)NB * CC * WW];  // values
__device__ bf16  g_sqt [(size_t)NB * WW * CC];   // softmax(Q) transposed [n][w][c]
__device__ bf16  g_Mb  [(size_t)NB * CC * CC];   // folded Wr@ctx^T (bf16)
__device__ float g_rows[NB * CC];                // sum(exp(keys)) per row
__device__ float g_ctxp[64 * 8 * 64 * 64];       // ctx partials
__device__ float g_ctx [64 * 64 * 64];           // normalized ctx

// ---------------- helpers (arch-neutral: ldmatrix / mma.sync / cp.async) ----
__device__ __forceinline__ uint32_t smem_u32(const void* p) {
    uint32_t a;
    asm("{ .reg .u64 t; cvta.to.shared.u64 t, %1; cvt.u32.u64 %0, t; }"
        : "=r"(a) : "l"(p));
    return a;
}
__device__ __forceinline__ void ldmx4(uint32_t* r, uint32_t addr) {
    asm volatile("ldmatrix.sync.aligned.m8n8.x4.shared.b16 {%0,%1,%2,%3}, [%4];"
                 : "=r"(r[0]), "=r"(r[1]), "=r"(r[2]), "=r"(r[3]) : "r"(addr));
}
__device__ __forceinline__ void mma_bf16(float* c, const uint32_t* a,
                                         const uint32_t b0, const uint32_t b1) {
    asm volatile(
        "mma.sync.aligned.m16n8k16.row.col.f32.bf16.bf16.f32 "
        "{%0,%1,%2,%3}, {%4,%5,%6,%7}, {%8,%9}, {%0,%1,%2,%3};"
        : "+f"(c[0]), "+f"(c[1]), "+f"(c[2]), "+f"(c[3])
        : "r"(a[0]), "r"(a[1]), "r"(a[2]), "r"(a[3]), "r"(b0), "r"(b1));
}
__device__ __forceinline__ void cp16(uint32_t dst, const void* src) {
    asm volatile("cp.async.cg.shared.global [%0], [%1], 16;" :: "r"(dst), "l"(src));
}
__device__ __forceinline__ void cp_commit() {
    asm volatile("cp.async.commit_group;");
}
template <int N>
__device__ __forceinline__ void cp_wait() {
    asm volatile("cp.async.wait_group %0;" :: "n"(N));
}

// ---------------------------------------------------------------------------
// HMMA GEMM body: D[128 x 128] = A[128 x 512] * B[colbase..+128, 512]^T
// bf16 K-major row-major operands. 5-stage cp.async pipeline, BK=32.
// ---------------------------------------------------------------------------
#define BK 32
#define STRD 40                      // smem row stride (80 B; ldmatrix conflict-free)
#define NSTAGE 5
#define STAGE_ELEMS (128 * STRD)
#define SMEMSZ (NSTAGE * STAGE_ELEMS * 2 * 2)   // 102400 B

__device__ __forceinline__ void mm_issue(
    const bf16* __restrict__ A, const bf16* __restrict__ B,
    bf16* As, bf16* Bs, int stage, int k0, int colbase, int r0, int c8)
{
    uint32_t sa = smem_u32(As + (size_t)stage * STAGE_ELEMS);
    uint32_t sb = smem_u32(Bs + (size_t)stage * STAGE_ELEMS);
#pragma unroll
    for (int u = 0; u < 2; ++u) {
        int row = r0 + u * 64;
        uint32_t so = (uint32_t)(row * STRD + c8) * 2;
        cp16(sa + so, A + (size_t)row * 512 + k0 + c8);
        cp16(sb + so, B + (size_t)(colbase + row) * 512 + k0 + c8);
    }
}

__device__ __forceinline__ void mm_body(
    const bf16* __restrict__ A,          // pre-offset to its 128-row slab
    const bf16* __restrict__ B,          // [8192 x 512] per-batch slab
    const float* __restrict__ bias,      // pre-offset [128]
    const float* __restrict__ resid,     // pre-offset rows (or nullptr)
    void* __restrict__ outp,             // pre-offset rows
    bool bf16out)
{
    extern __shared__ bf16 dsm[];
    bf16* As = dsm;
    bf16* Bs = dsm + (size_t)NSTAGE * STAGE_ELEMS;

    const int tid = threadIdx.x;
    const int lane = tid & 31;
    const int wid = tid >> 5;
    const int wm = (wid & 1) * 64;    // warp M base
    const int wn = (wid >> 1) * 32;   // warp N base
    const int colbase = blockIdx.x * 128;

    const int r0 = tid >> 2;                 // 0..63
    const int c8 = (tid & 3) << 3;           // 0,8,16,24

    float acc[4][4][4] = {};

    // prologue: stages 0..3
#pragma unroll
    for (int s = 0; s < 4; ++s) {
        mm_issue(A, B, As, Bs, s, s * BK, colbase, r0, c8);
        cp_commit();
    }

    for (int ch = 0; ch < 16; ++ch) {
        cp_wait<3>();
        __syncthreads();
        const int cur = ch % NSTAGE;
        const uint32_t sa = smem_u32(As + (size_t)cur * STAGE_ELEMS);
        const uint32_t sb = smem_u32(Bs + (size_t)cur * STAGE_ELEMS);

#pragma unroll
        for (int ks = 0; ks < 2; ++ks) {
            uint32_t a[4][4], b[2][4];
            const int kA = ks * 16 + ((lane >> 4) << 3);
            const int kB = ks * 16 + (((lane >> 3) & 1) << 3);
#pragma unroll
            for (int i = 0; i < 4; ++i)
                ldmx4(a[i], sa +
                      (uint32_t)((wm + i * 16 + (lane & 15)) * STRD + kA) * 2);
#pragma unroll
            for (int j2 = 0; j2 < 2; ++j2)
                ldmx4(b[j2], sb +
                      (uint32_t)((wn + j2 * 16 + (lane & 7) + ((lane >> 4) << 3))
                                 * STRD + kB) * 2);
#pragma unroll
            for (int i = 0; i < 4; ++i)
#pragma unroll
                for (int j = 0; j < 4; ++j)
                    mma_bf16(acc[i][j], a[i], b[j >> 1][(j & 1) * 2],
                             b[j >> 1][(j & 1) * 2 + 1]);
        }

        if (ch + 4 < 16)
            mm_issue(A, B, As, Bs, (ch + 4) % NSTAGE, (ch + 4) * BK,
                     colbase, r0, c8);
        cp_commit();  // always commit (possibly empty) to keep group accounting
    }

    // epilogue
    const int mrow = wm + (lane >> 2);
    const int ncol = colbase + wn + 2 * (lane & 3);
#pragma unroll
    for (int i = 0; i < 4; ++i) {
        int m0 = mrow + i * 16;
        float b0 = bias[m0], b1 = bias[m0 + 8];
#pragma unroll
        for (int j = 0; j < 4; ++j) {
            int n = ncol + j * 8;
            float* c = acc[i][j];
            if (bf16out) {
                bf16* o = (bf16*)outp;
                *(__nv_bfloat162*)(o + (size_t)m0 * WW + n) =
                    __floats2bfloat162_rn(c[0] + b0, c[1] + b0);
                *(__nv_bfloat162*)(o + (size_t)(m0 + 8) * WW + n) =
                    __floats2bfloat162_rn(c[2] + b1, c[3] + b1);
            } else {
                float* o = (float*)outp;
                float2 r0v = *(const float2*)(resid + (size_t)m0 * WW + n);
                float2 r1v = *(const float2*)(resid + (size_t)(m0 + 8) * WW + n);
                float2 o0 = { c[0] + b0 + r0v.x, c[1] + b0 + r0v.y };
                float2 o1 = { c[2] + b1 + r1v.x, c[3] + b1 + r1v.y };
                *(float2*)(o + (size_t)m0 * WW + n) = o0;
                *(float2*)(o + (size_t)(m0 + 8) * WW + n) = o1;
            }
        }
    }
}

// ---------------------------------------------------------------------------
// conversions / init
// ---------------------------------------------------------------------------
__global__ void __launch_bounds__(256)
k_convw(const float* __restrict__ s, bf16* __restrict__ d)
{
    int i = (blockIdx.x * 256 + threadIdx.x) * 4;
    float4 v = *(const float4*)(s + i);
    __nv_bfloat162 o[2];
    o[0] = __floats2bfloat162_rn(v.x, v.y);
    o[1] = __floats2bfloat162_rn(v.z, v.w);
    *(uint2*)(d + i) = *(uint2*)o;
}

__global__ void __launch_bounds__(256) k_zero()
{
    g_rows[blockIdx.x * 256 + threadIdx.x] = 0.f;
}

// 64x64 transpose tiles: 128B-coalesced reads and (bf16x2-packed) writes
__global__ void __launch_bounds__(256)
k_convx(const float* __restrict__ x)
{
    __shared__ float tile[64][65];
    int n = blockIdx.z, c0 = blockIdx.y * 64, w0 = blockIdx.x * 64;
    int t = threadIdx.x;
    int tx = t & 63, ty = t >> 6;            // read: 64 w per row, 4 rows/pass
    const float* xb = x + (size_t)n * CC * WW;
#pragma unroll
    for (int i = ty; i < 64; i += 4)
        tile[i][tx] = xb[(size_t)(c0 + i) * WW + w0 + tx];
    __syncthreads();
    bf16* ob = g_xt + (size_t)n * WW * CC;
    int cpair = (t & 31) * 2, wr = t >> 5;   // write: 32 c-pairs, 8 rows/pass
#pragma unroll
    for (int i = wr; i < 64; i += 8) {
        __nv_bfloat162 v = __floats2bfloat162_rn(tile[cpair][i], tile[cpair + 1][i]);
        *(__nv_bfloat162*)(ob + (size_t)(w0 + i) * CC + c0 + cpair) = v;
    }
}

// ---------------------------------------------------------------------------
// GEMM wrappers
// ---------------------------------------------------------------------------
__global__ void __launch_bounds__(256, 2)
k_proj(const float* __restrict__ bk, const float* __restrict__ bq,
       const float* __restrict__ bv)
{
    int mtile = blockIdx.y;
    int sect = mtile >> 2;
    int mbrow = (mtile & 3) * 128;
    int n = blockIdx.z;
    const bf16* A = g_wb + (size_t)sect * CC * CC + (size_t)mbrow * CC;
    const bf16* B = g_xt + (size_t)n * WW * CC;
    const float* bias = (sect == 0 ? bk : sect == 1 ? bq : bv) + mbrow;
    bf16* out = (sect == 0 ? g_keysb : sect == 1 ? g_querb : g_valsb)
                + (size_t)n * CC * WW + (size_t)mbrow * WW;
    mm_body(A, B, bias, nullptr, out, true);
}

__global__ void __launch_bounds__(256, 2)
k_out(const float* __restrict__ x, const float* __restrict__ br,
      float* __restrict__ out)
{
    int mbrow = blockIdx.y * 128;
    int n = blockIdx.z;
    const bf16* A = g_Mb + (size_t)n * CC * CC + (size_t)mbrow * CC;
    const bf16* B = g_sqt + (size_t)n * WW * CC;
    const float* resid = x + (size_t)n * CC * WW + (size_t)mbrow * WW;
    float* O = out + (size_t)n * CC * WW + (size_t)mbrow * WW;
    mm_body(A, B, br + mbrow, resid, O, false);
}

// ---------------------------------------------------------------------------
// ctx partials: exp(keys) @ V^T over 1024-wide w chunks + fused row sums
// ---------------------------------------------------------------------------
__global__ void __launch_bounds__(256) k_ctx()
{
    int nh = blockIdx.x, chunk = blockIdx.y, t = threadIdx.x;
    __shared__ float eK[64][33];
    __shared__ float Vs[64][33];

    int rowbase = nh * 64;
    int wbase = chunk * 1024;
    int lr = t >> 2;
    int lc = (t & 3) << 3;
    const uint4* kq = (const uint4*)(g_keysb + (size_t)(rowbase + lr) * WW + wbase + lc);
    const uint4* vq = (const uint4*)(g_valsb + (size_t)(rowbase + lr) * WW + wbase + lc);

    int k0 = (t >> 4) << 2;
    int v0 = (t & 15) << 2;
    float acc[4][4] = {};
    float srow = 0.f;   // partial sum of exp(keys) for row lr over this chunk

    for (int c = 0; c < 32; ++c) {
        __syncthreads();
        uint4 kd = kq[c * 4];
        uint4 vd = vq[c * 4];
        const __nv_bfloat162* kh = (const __nv_bfloat162*)&kd;
        const __nv_bfloat162* vh = (const __nv_bfloat162*)&vd;
#pragma unroll
        for (int i = 0; i < 4; ++i) {
            float2 kf = __bfloat1622float2(kh[i]);
            float2 vf = __bfloat1622float2(vh[i]);
            float e0 = __expf(kf.x), e1 = __expf(kf.y);
            srow += e0 + e1;
            eK[lr][lc + 2 * i + 0] = e0;
            eK[lr][lc + 2 * i + 1] = e1;
            Vs[lr][lc + 2 * i + 0] = vf.x;
            Vs[lr][lc + 2 * i + 1] = vf.y;
        }
        __syncthreads();
#pragma unroll
        for (int tt = 0; tt < 32; ++tt) {
            float a_[4], b_[4];
#pragma unroll
            for (int i = 0; i < 4; ++i) a_[i] = eK[k0 + i][tt];
#pragma unroll
            for (int j = 0; j < 4; ++j) b_[j] = Vs[v0 + j][tt];
#pragma unroll
            for (int i = 0; i < 4; ++i)
#pragma unroll
                for (int j = 0; j < 4; ++j)
                    acc[i][j] = fmaf(a_[i], b_[j], acc[i][j]);
        }
    }
    // fused row-sum: reduce the 4 loader threads of each row, one atomic each
    srow += __shfl_xor_sync(0xffffffffu, srow, 1);
    srow += __shfl_xor_sync(0xffffffffu, srow, 2);
    if ((t & 3) == 0) atomicAdd(&g_rows[rowbase + lr], srow);

    float* op = g_ctxp + (size_t)(nh * 8 + chunk) * 4096;
#pragma unroll
    for (int i = 0; i < 4; ++i)
#pragma unroll
        for (int j = 0; j < 4; ++j)
            op[(k0 + i) * 64 + v0 + j] = acc[i][j];
}

__global__ void __launch_bounds__(256) k_reduce()
{
    int nh = blockIdx.x, t = threadIdx.x;
    for (int e = t; e < 4096; e += 256) {
        float sum = 0.f;
#pragma unroll
        for (int c = 0; c < 8; ++c) sum += g_ctxp[(size_t)(nh * 8 + c) * 4096 + e];
        int k = e >> 6;
        g_ctx[(size_t)nh * 4096 + e] = sum / g_rows[nh * 64 + k];
    }
}

// ---------------------------------------------------------------------------
// M[n][c][h*64+k] = sum_v Wr[c][h*64+v] * ctx[n][h][k][v]  (bf16 out)
// ---------------------------------------------------------------------------
__global__ void __launch_bounds__(256) k_M(const float* __restrict__ Wr)
{
    int ct = blockIdx.x, h = blockIdx.y, n = blockIdx.z;
    __shared__ float Ws[64][65];
    __shared__ float Cs[64][65];
    int t = threadIdx.x;

    for (int e = t; e < 4096; e += 256) {
        int r = e >> 6, c = e & 63;
        Ws[r][c] = Wr[(size_t)(ct * 64 + r) * 512 + h * 64 + c];
        Cs[r][c] = g_ctx[(size_t)(n * 8 + h) * 4096 + e];
    }
    __syncthreads();

    int c0 = (t >> 4) << 2;
    int k0 = (t & 15) << 2;
    float acc[4][4] = {};
    for (int v = 0; v < 64; ++v) {
        float a_[4], b_[4];
#pragma unroll
        for (int i = 0; i < 4; ++i) a_[i] = Ws[c0 + i][v];
#pragma unroll
        for (int j = 0; j < 4; ++j) b_[j] = Cs[k0 + j][v];
#pragma unroll
        for (int i = 0; i < 4; ++i)
#pragma unroll
            for (int j = 0; j < 4; ++j)
                acc[i][j] = fmaf(a_[i], b_[j], acc[i][j]);
    }
#pragma unroll
    for (int i = 0; i < 4; ++i)
#pragma unroll
        for (int j = 0; j < 4; ++j)
            g_Mb[(size_t)n * 262144 + (size_t)(ct * 64 + c0 + i) * 512 + h * 64 + k0 + j]
                = __float2bfloat16(acc[i][j]);
}

// ---------------------------------------------------------------------------
// column softmax of queries (64 channels per head); 2 w-positions per thread;
// output transposed to [n][w][c]
// ---------------------------------------------------------------------------
__global__ void __launch_bounds__(256) k_softq()
{
    int cid = blockIdx.x * 256 + threadIdx.x;   // 0..262143
    int n = cid >> 15;
    int h = (cid >> 12) & 7;
    int w = (cid & 4095) * 2;
    const bf16* base = g_querb + ((size_t)(n * CC + h * 64)) * WW + w;

    __nv_bfloat162 kd[64];
#pragma unroll
    for (int k = 0; k < 64; ++k)
        kd[k] = *(const __nv_bfloat162*)(base + (size_t)k * WW);

    __nv_bfloat162 mx = kd[0];
#pragma unroll
    for (int k = 1; k < 64; ++k) mx = __hmax2(mx, kd[k]);
    float m0 = __low2float(mx), m1 = __high2float(mx);

    float s0 = 0.f, s1 = 0.f;
#pragma unroll
    for (int k = 0; k < 64; ++k) {
        float2 f = __bfloat1622float2(kd[k]);
        float e0 = __expf(f.x - m0);
        float e1 = __expf(f.y - m1);
        s0 += e0; s1 += e1;
        kd[k] = __floats2bfloat162_rn(e0, e1);
    }
    float inv0 = 1.0f / s0, inv1 = 1.0f / s1;

    __nv_bfloat162 o[32];
    // w row
#pragma unroll
    for (int j = 0; j < 32; ++j)
        o[j] = __floats2bfloat162_rn(__low2float(kd[2 * j]) * inv0,
                                     __low2float(kd[2 * j + 1]) * inv0);
    uint4* dst0 = (uint4*)(g_sqt + ((size_t)n * WW + w) * CC + h * 64);
#pragma unroll
    for (int q = 0; q < 8; ++q) dst0[q] = ((uint4*)o)[q];
    // w+1 row
#pragma unroll
    for (int j = 0; j < 32; ++j)
        o[j] = __floats2bfloat162_rn(__high2float(kd[2 * j]) * inv1,
                                     __high2float(kd[2 * j + 1]) * inv1);
    uint4* dst1 = (uint4*)(g_sqt + ((size_t)n * WW + w + 1) * CC + h * 64);
#pragma unroll
    for (int q = 0; q < 8; ++q) dst1[q] = ((uint4*)o)[q];
}

// ---------------------------------------------------------------------------
extern "C" void kernel_launch(void* const* d_in, const int* in_sizes, int n_in,
                              void* d_out, int out_size)
{
    const float* x  = (const float*)d_in[0];
    const float* Wk = (const float*)d_in[1];
    const float* bk = (const float*)d_in[2];
    const float* Wq = (const float*)d_in[3];
    const float* bq = (const float*)d_in[4];
    const float* Wv = (const float*)d_in[5];
    const float* bv = (const float*)d_in[6];
    const float* Wr = (const float*)d_in[7];
    const float* br = (const float*)d_in[8];
    float* out = (float*)d_out;

    bf16* wb;
    cudaGetSymbolAddress((void**)&wb, g_wb);

    cudaFuncSetAttribute(k_proj, cudaFuncAttributeMaxDynamicSharedMemorySize, SMEMSZ);
    cudaFuncSetAttribute(k_out,  cudaFuncAttributeMaxDynamicSharedMemorySize, SMEMSZ);

    k_convw<<<256, 256>>>(Wk, wb);
    k_convw<<<256, 256>>>(Wq, wb + 262144);
    k_convw<<<256, 256>>>(Wv, wb + 524288);
    k_zero<<<16, 256>>>();
    k_convx<<<dim3(128, 8, 8), 256>>>(x);
    k_proj<<<dim3(64, 12, 8), 256, SMEMSZ>>>(bk, bq, bv);
    k_ctx<<<dim3(64, 8), 256>>>();
    k_reduce<<<64, 256>>>();
    k_M<<<dim3(8, 8, 8), 256>>>(Wr);
    k_softq<<<1024, 256>>>();
    k_out<<<dim3(64, 4, 8), 256, SMEMSZ>>>(x, br, out);
}

// round 6
// speedup vs baseline: 4.9814x; 1.1837x over previous
#include <cuda_runtime.h>
#include <cuda_bf16.h>
#include <cstdint>
#include <cstddef>

#define NB 8
#define CC 512
#define WW 8192
#define HH 8

typedef __nv_bfloat16 bf16;

// ---------------- scratch (device globals; allocation-free) ----------------
__device__ bf16  g_xt  [(size_t)NB * WW * CC];   // x transposed [n][w][c] bf16
__device__ bf16  g_wb  [3 * CC * CC];            // Wk,Wq,Wv bf16
__device__ bf16  g_keysb[(size_t)NB * CC * WW];  // keys [n][c][w] bf16
__device__ bf16  g_querb[(size_t)NB * CC * WW];  // queries
__device__ bf16  g_valsb[(size_t)NB * CC * WW];  // values
__device__ bf16  g_sqt [(size_t)NB * WW * CC];   // softmax(Q) transposed [n][w][c]
__device__ bf16  g_Mb  [(size_t)NB * CC * CC];   // folded Wr@ctx^T (bf16)
__device__ float g_rows[NB * CC];                // sum(exp(keys)) per row
__device__ float g_ctxp[64 * 8 * 64 * 64];       // ctx partials

// ---------------- helpers (arch-neutral: ldmatrix / mma.sync / cp.async) ----
__device__ __forceinline__ uint32_t smem_u32(const void* p) {
    uint32_t a;
    asm("{ .reg .u64 t; cvta.to.shared.u64 t, %1; cvt.u32.u64 %0, t; }"
        : "=r"(a) : "l"(p));
    return a;
}
__device__ __forceinline__ void ldmx4(uint32_t* r, uint32_t addr) {
    asm volatile("ldmatrix.sync.aligned.m8n8.x4.shared.b16 {%0,%1,%2,%3}, [%4];"
                 : "=r"(r[0]), "=r"(r[1]), "=r"(r[2]), "=r"(r[3]) : "r"(addr));
}
__device__ __forceinline__ void mma_bf16(float* c, const uint32_t* a,
                                         const uint32_t b0, const uint32_t b1) {
    asm volatile(
        "mma.sync.aligned.m16n8k16.row.col.f32.bf16.bf16.f32 "
        "{%0,%1,%2,%3}, {%4,%5,%6,%7}, {%8,%9}, {%0,%1,%2,%3};"
        : "+f"(c[0]), "+f"(c[1]), "+f"(c[2]), "+f"(c[3])
        : "r"(a[0]), "r"(a[1]), "r"(a[2]), "r"(a[3]), "r"(b0), "r"(b1));
}
__device__ __forceinline__ void cp16(uint32_t dst, const void* src) {
    asm volatile("cp.async.cg.shared.global [%0], [%1], 16;" :: "r"(dst), "l"(src));
}
__device__ __forceinline__ void cp_commit() {
    asm volatile("cp.async.commit_group;");
}
template <int N>
__device__ __forceinline__ void cp_wait() {
    asm volatile("cp.async.wait_group %0;" :: "n"(N));
}

// ---------------------------------------------------------------------------
// HMMA GEMM body: D[128 x 128] = A[128 x 512] * B[colbase..+128, 512]^T
// bf16 K-major row-major operands. 5-stage cp.async pipeline, BK=32.
// ---------------------------------------------------------------------------
#define BK 32
#define STRD 40                      // smem row stride (80 B; ldmatrix conflict-free)
#define NSTAGE 5
#define STAGE_ELEMS (128 * STRD)
#define SMEMSZ (NSTAGE * STAGE_ELEMS * 2 * 2)   // 102400 B

__device__ __forceinline__ void mm_issue(
    const bf16* __restrict__ A, const bf16* __restrict__ B,
    bf16* As, bf16* Bs, int stage, int k0, int colbase, int r0, int c8)
{
    uint32_t sa = smem_u32(As + (size_t)stage * STAGE_ELEMS);
    uint32_t sb = smem_u32(Bs + (size_t)stage * STAGE_ELEMS);
#pragma unroll
    for (int u = 0; u < 2; ++u) {
        int row = r0 + u * 64;
        uint32_t so = (uint32_t)(row * STRD + c8) * 2;
        cp16(sa + so, A + (size_t)row * 512 + k0 + c8);
        cp16(sb + so, B + (size_t)(colbase + row) * 512 + k0 + c8);
    }
}

__device__ __forceinline__ void mm_body(
    const bf16* __restrict__ A,          // pre-offset to its 128-row slab
    const bf16* __restrict__ B,          // [8192 x 512] per-batch slab
    const float* __restrict__ bias,      // pre-offset [128]
    const float* __restrict__ resid,     // pre-offset rows (or nullptr)
    void* __restrict__ outp,             // pre-offset rows
    bool bf16out)
{
    extern __shared__ bf16 dsm[];
    bf16* As = dsm;
    bf16* Bs = dsm + (size_t)NSTAGE * STAGE_ELEMS;

    const int tid = threadIdx.x;
    const int lane = tid & 31;
    const int wid = tid >> 5;
    const int wm = (wid & 1) * 64;    // warp M base
    const int wn = (wid >> 1) * 32;   // warp N base
    const int colbase = blockIdx.x * 128;

    const int r0 = tid >> 2;                 // 0..63
    const int c8 = (tid & 3) << 3;           // 0,8,16,24

    float acc[4][4][4] = {};

    // prologue: stages 0..3
#pragma unroll
    for (int s = 0; s < 4; ++s) {
        mm_issue(A, B, As, Bs, s, s * BK, colbase, r0, c8);
        cp_commit();
    }

    for (int ch = 0; ch < 16; ++ch) {
        cp_wait<3>();
        __syncthreads();
        const int cur = ch % NSTAGE;
        const uint32_t sa = smem_u32(As + (size_t)cur * STAGE_ELEMS);
        const uint32_t sb = smem_u32(Bs + (size_t)cur * STAGE_ELEMS);

#pragma unroll
        for (int ks = 0; ks < 2; ++ks) {
            uint32_t a[4][4], b[2][4];
            const int kA = ks * 16 + ((lane >> 4) << 3);
            const int kB = ks * 16 + (((lane >> 3) & 1) << 3);
#pragma unroll
            for (int i = 0; i < 4; ++i)
                ldmx4(a[i], sa +
                      (uint32_t)((wm + i * 16 + (lane & 15)) * STRD + kA) * 2);
#pragma unroll
            for (int j2 = 0; j2 < 2; ++j2)
                ldmx4(b[j2], sb +
                      (uint32_t)((wn + j2 * 16 + (lane & 7) + ((lane >> 4) << 3))
                                 * STRD + kB) * 2);
#pragma unroll
            for (int i = 0; i < 4; ++i)
#pragma unroll
                for (int j = 0; j < 4; ++j)
                    mma_bf16(acc[i][j], a[i], b[j >> 1][(j & 1) * 2],
                             b[j >> 1][(j & 1) * 2 + 1]);
        }

        if (ch + 4 < 16)
            mm_issue(A, B, As, Bs, (ch + 4) % NSTAGE, (ch + 4) * BK,
                     colbase, r0, c8);
        cp_commit();  // always commit (possibly empty) to keep group accounting
    }

    // epilogue
    const int mrow = wm + (lane >> 2);
    const int ncol = colbase + wn + 2 * (lane & 3);
#pragma unroll
    for (int i = 0; i < 4; ++i) {
        int m0 = mrow + i * 16;
        float b0 = bias[m0], b1 = bias[m0 + 8];
#pragma unroll
        for (int j = 0; j < 4; ++j) {
            int n = ncol + j * 8;
            float* c = acc[i][j];
            if (bf16out) {
                bf16* o = (bf16*)outp;
                *(__nv_bfloat162*)(o + (size_t)m0 * WW + n) =
                    __floats2bfloat162_rn(c[0] + b0, c[1] + b0);
                *(__nv_bfloat162*)(o + (size_t)(m0 + 8) * WW + n) =
                    __floats2bfloat162_rn(c[2] + b1, c[3] + b1);
            } else {
                float* o = (float*)outp;
                float2 r0v = *(const float2*)(resid + (size_t)m0 * WW + n);
                float2 r1v = *(const float2*)(resid + (size_t)(m0 + 8) * WW + n);
                float2 o0 = { c[0] + b0 + r0v.x, c[1] + b0 + r0v.y };
                float2 o1 = { c[2] + b1 + r1v.x, c[3] + b1 + r1v.y };
                *(float2*)(o + (size_t)m0 * WW + n) = o0;
                *(float2*)(o + (size_t)(m0 + 8) * WW + n) = o1;
            }
        }
    }
}

// ---------------------------------------------------------------------------
// conversions / init (first convw call also zeroes g_rows)
// ---------------------------------------------------------------------------
__global__ void __launch_bounds__(256)
k_convw(const float* __restrict__ s, bf16* __restrict__ d, int zero_rows)
{
    int gid = blockIdx.x * 256 + threadIdx.x;
    if (zero_rows && gid < NB * CC) g_rows[gid] = 0.f;
    int i = gid * 4;
    float4 v = *(const float4*)(s + i);
    __nv_bfloat162 o[2];
    o[0] = __floats2bfloat162_rn(v.x, v.y);
    o[1] = __floats2bfloat162_rn(v.z, v.w);
    *(uint2*)(d + i) = *(uint2*)o;
}

// 64x64 transpose tiles: 128B-coalesced reads and (bf16x2-packed) writes
__global__ void __launch_bounds__(256)
k_convx(const float* __restrict__ x)
{
    __shared__ float tile[64][65];
    int n = blockIdx.z, c0 = blockIdx.y * 64, w0 = blockIdx.x * 64;
    int t = threadIdx.x;
    int tx = t & 63, ty = t >> 6;            // read: 64 w per row, 4 rows/pass
    const float* xb = x + (size_t)n * CC * WW;
#pragma unroll
    for (int i = ty; i < 64; i += 4)
        tile[i][tx] = xb[(size_t)(c0 + i) * WW + w0 + tx];
    __syncthreads();
    bf16* ob = g_xt + (size_t)n * WW * CC;
    int cpair = (t & 31) * 2, wr = t >> 5;   // write: 32 c-pairs, 8 rows/pass
#pragma unroll
    for (int i = wr; i < 64; i += 8) {
        __nv_bfloat162 v = __floats2bfloat162_rn(tile[cpair][i], tile[cpair + 1][i]);
        *(__nv_bfloat162*)(ob + (size_t)(w0 + i) * CC + c0 + cpair) = v;
    }
}

// ---------------------------------------------------------------------------
// GEMM wrappers
// ---------------------------------------------------------------------------
__global__ void __launch_bounds__(256, 2)
k_proj(const float* __restrict__ bk, const float* __restrict__ bq,
       const float* __restrict__ bv)
{
    int mtile = blockIdx.y;
    int sect = mtile >> 2;
    int mbrow = (mtile & 3) * 128;
    int n = blockIdx.z;
    const bf16* A = g_wb + (size_t)sect * CC * CC + (size_t)mbrow * CC;
    const bf16* B = g_xt + (size_t)n * WW * CC;
    const float* bias = (sect == 0 ? bk : sect == 1 ? bq : bv) + mbrow;
    bf16* out = (sect == 0 ? g_keysb : sect == 1 ? g_querb : g_valsb)
                + (size_t)n * CC * WW + (size_t)mbrow * WW;
    mm_body(A, B, bias, nullptr, out, true);
}

__global__ void __launch_bounds__(256, 2)
k_out(const float* __restrict__ x, const float* __restrict__ br,
      float* __restrict__ out)
{
    int mbrow = blockIdx.y * 128;
    int n = blockIdx.z;
    const bf16* A = g_Mb + (size_t)n * CC * CC + (size_t)mbrow * CC;
    const bf16* B = g_sqt + (size_t)n * WW * CC;
    const float* resid = x + (size_t)n * CC * WW + (size_t)mbrow * WW;
    float* O = out + (size_t)n * CC * WW + (size_t)mbrow * WW;
    mm_body(A, B, br + mbrow, resid, O, false);
}

// ---------------------------------------------------------------------------
// ctx partials via HMMA: exp(K) @ V^T over 1024-wide w chunks, fused row sums.
// grid (64 nh, 8 chunks), 256 threads. smem [64][72] bf16, double-buffered.
// ---------------------------------------------------------------------------
#define CSTRD 72

__global__ void __launch_bounds__(256) k_ctx()
{
    __shared__ bf16 Ks[2][64 * CSTRD];
    __shared__ bf16 Vs[2][64 * CSTRD];

    int nh = blockIdx.x, chunk = blockIdx.y, t = threadIdx.x;
    int lane = t & 31, wid = t >> 5;
    int rowbase = nh * 64;
    int wbase = chunk * 1024;
    int lr = t >> 2;                 // 0..63 load row
    int seg = (t & 3) * 16;          // 0,16,32,48 (16 bf16 per thread)
    const bf16* kg = g_keysb + (size_t)(rowbase + lr) * WW + wbase + seg;
    const bf16* vg = g_valsb + (size_t)(rowbase + lr) * WW + wbase + seg;

    int wm = (wid & 3) * 16;         // warp out rows
    int wn = (wid >> 2) * 32;        // warp out cols

    float acc[4][4] = {};            // [n-chunk of 8][c0..c3]
    float srow = 0.f;

    uint4 kr[2], vr[2];
    kr[0] = *(const uint4*)kg;       kr[1] = *(const uint4*)(kg + 8);
    vr[0] = *(const uint4*)vg;       vr[1] = *(const uint4*)(vg + 8);

    for (int s = 0; s < 16; ++s) {
        const int b = s & 1;
        // exp(K) -> bf16 + STS; V STS
        uint4 ke[2];
#pragma unroll
        for (int u = 0; u < 2; ++u) {
            const __nv_bfloat162* kh = (const __nv_bfloat162*)&kr[u];
            __nv_bfloat162* eo = (__nv_bfloat162*)&ke[u];
#pragma unroll
            for (int i = 0; i < 4; ++i) {
                float2 f = __bfloat1622float2(kh[i]);
                float e0 = __expf(f.x), e1 = __expf(f.y);
                srow += e0 + e1;
                eo[i] = __floats2bfloat162_rn(e0, e1);
            }
        }
        bf16* kst = &Ks[b][lr * CSTRD + seg];
        bf16* vst = &Vs[b][lr * CSTRD + seg];
        *(uint4*)kst = ke[0];        *(uint4*)(kst + 8) = ke[1];
        *(uint4*)vst = vr[0];        *(uint4*)(vst + 8) = vr[1];
        __syncthreads();
        if (s < 15) {                 // prefetch next slice (hidden under mma)
            const bf16* kg2 = kg + (s + 1) * 64;
            const bf16* vg2 = vg + (s + 1) * 64;
            kr[0] = *(const uint4*)kg2; kr[1] = *(const uint4*)(kg2 + 8);
            vr[0] = *(const uint4*)vg2; vr[1] = *(const uint4*)(vg2 + 8);
        }
        const uint32_t sk = smem_u32(&Ks[b][0]);
        const uint32_t sv = smem_u32(&Vs[b][0]);
#pragma unroll
        for (int ks = 0; ks < 4; ++ks) {
            uint32_t a[4], bb[2][4];
            const int kA = ks * 16 + ((lane >> 4) << 3);
            const int kB = ks * 16 + (((lane >> 3) & 1) << 3);
            ldmx4(a, sk + (uint32_t)((wm + (lane & 15)) * CSTRD + kA) * 2);
#pragma unroll
            for (int j2 = 0; j2 < 2; ++j2)
                ldmx4(bb[j2], sv +
                      (uint32_t)((wn + j2 * 16 + (lane & 7) + ((lane >> 4) << 3))
                                 * CSTRD + kB) * 2);
#pragma unroll
            for (int j = 0; j < 4; ++j)
                mma_bf16(acc[j], a, bb[j >> 1][(j & 1) * 2],
                         bb[j >> 1][(j & 1) * 2 + 1]);
        }
        // no trailing sync: double buffer; next iteration's sync protects reuse
    }

    // fused row sums: 4 loader threads per row
    srow += __shfl_xor_sync(0xffffffffu, srow, 1);
    srow += __shfl_xor_sync(0xffffffffu, srow, 2);
    if ((t & 3) == 0) atomicAdd(&g_rows[rowbase + lr], srow);

    float* op = g_ctxp + (size_t)(nh * 8 + chunk) * 4096;
    int r0 = wm + (lane >> 2);
    int c0 = wn + (lane & 3) * 2;
#pragma unroll
    for (int j = 0; j < 4; ++j) {
        int c = c0 + j * 8;
        op[r0 * 64 + c]           = acc[j][0];
        op[r0 * 64 + c + 1]       = acc[j][1];
        op[(r0 + 8) * 64 + c]     = acc[j][2];
        op[(r0 + 8) * 64 + c + 1] = acc[j][3];
    }
}

// ---------------------------------------------------------------------------
// M[n][c][h*64+k] = sum_v Wr[c][h*64+v] * ctx[n][h][k][v]  (bf16 out)
// ctx partial reduction + 1/rowsum fused here (ctxp is L2-resident).
// ---------------------------------------------------------------------------
__global__ void __launch_bounds__(256) k_M(const float* __restrict__ Wr)
{
    int ct = blockIdx.x, h = blockIdx.y, n = blockIdx.z;
    __shared__ float Ws[64][65];
    __shared__ float Cs[64][65];
    int t = threadIdx.x;
    int nh = n * 8 + h;

    for (int e = t; e < 4096; e += 256) {
        int r = e >> 6, c = e & 63;
        Ws[r][c] = Wr[(size_t)(ct * 64 + r) * 512 + h * 64 + c];
        float sum = 0.f;
#pragma unroll
        for (int ch = 0; ch < 8; ++ch)
            sum += g_ctxp[(size_t)(nh * 8 + ch) * 4096 + e];
        Cs[r][c] = sum / g_rows[nh * 64 + r];
    }
    __syncthreads();

    int c0 = (t >> 4) << 2;
    int k0 = (t & 15) << 2;
    float acc[4][4] = {};
    for (int v = 0; v < 64; ++v) {
        float a_[4], b_[4];
#pragma unroll
        for (int i = 0; i < 4; ++i) a_[i] = Ws[c0 + i][v];
#pragma unroll
        for (int j = 0; j < 4; ++j) b_[j] = Cs[k0 + j][v];
#pragma unroll
        for (int i = 0; i < 4; ++i)
#pragma unroll
            for (int j = 0; j < 4; ++j)
                acc[i][j] = fmaf(a_[i], b_[j], acc[i][j]);
    }
#pragma unroll
    for (int i = 0; i < 4; ++i)
#pragma unroll
        for (int j = 0; j < 4; ++j)
            g_Mb[(size_t)n * 262144 + (size_t)(ct * 64 + c0 + i) * 512 + h * 64 + k0 + j]
                = __float2bfloat16(acc[i][j]);
}

// ---------------------------------------------------------------------------
// column softmax of queries (64 channels per head); 2 w-positions per thread;
// output transposed to [n][w][c]
// ---------------------------------------------------------------------------
__global__ void __launch_bounds__(256) k_softq()
{
    int cid = blockIdx.x * 256 + threadIdx.x;   // 0..262143
    int n = cid >> 15;
    int h = (cid >> 12) & 7;
    int w = (cid & 4095) * 2;
    const bf16* base = g_querb + ((size_t)(n * CC + h * 64)) * WW + w;

    __nv_bfloat162 kd[64];
#pragma unroll
    for (int k = 0; k < 64; ++k)
        kd[k] = *(const __nv_bfloat162*)(base + (size_t)k * WW);

    __nv_bfloat162 mx = kd[0];
#pragma unroll
    for (int k = 1; k < 64; ++k) mx = __hmax2(mx, kd[k]);
    float m0 = __low2float(mx), m1 = __high2float(mx);

    float s0 = 0.f, s1 = 0.f;
#pragma unroll
    for (int k = 0; k < 64; ++k) {
        float2 f = __bfloat1622float2(kd[k]);
        float e0 = __expf(f.x - m0);
        float e1 = __expf(f.y - m1);
        s0 += e0; s1 += e1;
        kd[k] = __floats2bfloat162_rn(e0, e1);
    }
    float inv0 = 1.0f / s0, inv1 = 1.0f / s1;

    __nv_bfloat162 o[32];
#pragma unroll
    for (int j = 0; j < 32; ++j)
        o[j] = __floats2bfloat162_rn(__low2float(kd[2 * j]) * inv0,
                                     __low2float(kd[2 * j + 1]) * inv0);
    uint4* dst0 = (uint4*)(g_sqt + ((size_t)n * WW + w) * CC + h * 64);
#pragma unroll
    for (int q = 0; q < 8; ++q) dst0[q] = ((uint4*)o)[q];
#pragma unroll
    for (int j = 0; j < 32; ++j)
        o[j] = __floats2bfloat162_rn(__high2float(kd[2 * j]) * inv1,
                                     __high2float(kd[2 * j + 1]) * inv1);
    uint4* dst1 = (uint4*)(g_sqt + ((size_t)n * WW + w + 1) * CC + h * 64);
#pragma unroll
    for (int q = 0; q < 8; ++q) dst1[q] = ((uint4*)o)[q];
}

// ---------------------------------------------------------------------------
extern "C" void kernel_launch(void* const* d_in, const int* in_sizes, int n_in,
                              void* d_out, int out_size)
{
    const float* x  = (const float*)d_in[0];
    const float* Wk = (const float*)d_in[1];
    const float* bk = (const float*)d_in[2];
    const float* Wq = (const float*)d_in[3];
    const float* bq = (const float*)d_in[4];
    const float* Wv = (const float*)d_in[5];
    const float* bv = (const float*)d_in[6];
    const float* Wr = (const float*)d_in[7];
    const float* br = (const float*)d_in[8];
    float* out = (float*)d_out;

    bf16* wb;
    cudaGetSymbolAddress((void**)&wb, g_wb);

    cudaFuncSetAttribute(k_proj, cudaFuncAttributeMaxDynamicSharedMemorySize, SMEMSZ);
    cudaFuncSetAttribute(k_out,  cudaFuncAttributeMaxDynamicSharedMemorySize, SMEMSZ);

    k_convw<<<256, 256>>>(Wk, wb, 1);
    k_convw<<<256, 256>>>(Wq, wb + 262144, 0);
    k_convw<<<256, 256>>>(Wv, wb + 524288, 0);
    k_convx<<<dim3(128, 8, 8), 256>>>(x);
    k_proj<<<dim3(64, 12, 8), 256, SMEMSZ>>>(bk, bq, bv);
    k_ctx<<<dim3(64, 8), 256>>>();
    k_M<<<dim3(8, 8, 8), 256>>>(Wr);
    k_softq<<<1024, 256>>>();
    k_out<<<dim3(64, 4, 8), 256, SMEMSZ>>>(x, br, out);
}

// round 8
// speedup vs baseline: 4.9882x; 1.0014x over previous
#include <cuda_runtime.h>
#include <cuda_bf16.h>
#include <cstdint>
#include <cstddef>

#define NB 8
#define CC 512
#define WW 8192
#define HH 8

typedef __nv_bfloat16 bf16;

// ---------------- scratch (device globals; allocation-free) ----------------
__device__ bf16  g_xt  [(size_t)NB * WW * CC];   // x transposed [n][w][c] bf16
__device__ bf16  g_wb  [3 * CC * CC];            // Wk,Wq,Wv bf16
__device__ bf16  g_keysb[(size_t)NB * CC * WW];  // keys [n][c][w] bf16
__device__ bf16  g_querb[(size_t)NB * CC * WW];  // softmax(Q) [n][c][w] bf16
__device__ bf16  g_valsb[(size_t)NB * CC * WW];  // values
__device__ bf16  g_sqt [(size_t)NB * WW * CC];   // softmax(Q) transposed [n][w][c]
__device__ bf16  g_Mb  [(size_t)NB * CC * CC];   // folded Wr@ctx^T (bf16)
__device__ float g_rows[NB * CC];                // sum(exp(keys)) per row
__device__ float g_ctxp[64 * 8 * 64 * 64];       // ctx partials

// ---------------- helpers (arch-neutral: ldmatrix / mma.sync / cp.async) ----
__device__ __forceinline__ uint32_t smem_u32(const void* p) {
    uint32_t a;
    asm("{ .reg .u64 t; cvta.to.shared.u64 t, %1; cvt.u32.u64 %0, t; }"
        : "=r"(a) : "l"(p));
    return a;
}
__device__ __forceinline__ void ldmx4(uint32_t* r, uint32_t addr) {
    asm volatile("ldmatrix.sync.aligned.m8n8.x4.shared.b16 {%0,%1,%2,%3}, [%4];"
                 : "=r"(r[0]), "=r"(r[1]), "=r"(r[2]), "=r"(r[3]) : "r"(addr));
}
__device__ __forceinline__ void mma_bf16(float* c, const uint32_t* a,
                                         const uint32_t b0, const uint32_t b1) {
    asm volatile(
        "mma.sync.aligned.m16n8k16.row.col.f32.bf16.bf16.f32 "
        "{%0,%1,%2,%3}, {%4,%5,%6,%7}, {%8,%9}, {%0,%1,%2,%3};"
        : "+f"(c[0]), "+f"(c[1]), "+f"(c[2]), "+f"(c[3])
        : "r"(a[0]), "r"(a[1]), "r"(a[2]), "r"(a[3]), "r"(b0), "r"(b1));
}
__device__ __forceinline__ void cp16(uint32_t dst, const void* src) {
    asm volatile("cp.async.cg.shared.global [%0], [%1], 16;" :: "r"(dst), "l"(src));
}
__device__ __forceinline__ void cp_commit() {
    asm volatile("cp.async.commit_group;");
}
template <int N>
__device__ __forceinline__ void cp_wait() {
    asm volatile("cp.async.wait_group %0;" :: "n"(N));
}

// ---------------------------------------------------------------------------
// HMMA GEMM body: D[128 x 128] = A[128 x 512] * B[colbase..+128, 512]^T
// bf16 K-major row-major operands. 5-stage cp.async pipeline, BK=32.
// mode: 0 = fp32 out + residual; 1 = bf16 out; 2 = bf16 out + column softmax
//       (per-warp over the 64 M-rows it owns == one head)
// ---------------------------------------------------------------------------
#define BK 32
#define STRD 40                      // smem row stride (80 B; ldmatrix conflict-free)
#define NSTAGE 5
#define STAGE_ELEMS (128 * STRD)
#define SMEMSZ (NSTAGE * STAGE_ELEMS * 2 * 2)   // 102400 B

__device__ __forceinline__ void mm_issue(
    const bf16* __restrict__ A, const bf16* __restrict__ B,
    bf16* As, bf16* Bs, int stage, int k0, int colbase, int r0, int c8)
{
    uint32_t sa = smem_u32(As + (size_t)stage * STAGE_ELEMS);
    uint32_t sb = smem_u32(Bs + (size_t)stage * STAGE_ELEMS);
#pragma unroll
    for (int u = 0; u < 2; ++u) {
        int row = r0 + u * 64;
        uint32_t so = (uint32_t)(row * STRD + c8) * 2;
        cp16(sa + so, A + (size_t)row * 512 + k0 + c8);
        cp16(sb + so, B + (size_t)(colbase + row) * 512 + k0 + c8);
    }
}

__device__ __forceinline__ void mm_body(
    const bf16* __restrict__ A,          // pre-offset to its 128-row slab
    const bf16* __restrict__ B,          // [8192 x 512] per-batch slab
    const float* __restrict__ bias,      // pre-offset [128]
    const float* __restrict__ resid,     // pre-offset rows (or nullptr)
    void* __restrict__ outp,             // pre-offset rows
    int mode)
{
    extern __shared__ bf16 dsm[];
    bf16* As = dsm;
    bf16* Bs = dsm + (size_t)NSTAGE * STAGE_ELEMS;

    const int tid = threadIdx.x;
    const int lane = tid & 31;
    const int wid = tid >> 5;
    const int wm = (wid & 1) * 64;    // warp M base
    const int wn = (wid >> 1) * 32;   // warp N base
    const int colbase = blockIdx.x * 128;

    const int r0 = tid >> 2;                 // 0..63
    const int c8 = (tid & 3) << 3;           // 0,8,16,24

    float acc[4][4][4] = {};

    // prologue: stages 0..3
#pragma unroll
    for (int s = 0; s < 4; ++s) {
        mm_issue(A, B, As, Bs, s, s * BK, colbase, r0, c8);
        cp_commit();
    }

    for (int ch = 0; ch < 16; ++ch) {
        cp_wait<3>();
        __syncthreads();
        const int cur = ch % NSTAGE;
        const uint32_t sa = smem_u32(As + (size_t)cur * STAGE_ELEMS);
        const uint32_t sb = smem_u32(Bs + (size_t)cur * STAGE_ELEMS);

#pragma unroll
        for (int ks = 0; ks < 2; ++ks) {
            uint32_t a[4][4], b[2][4];
            const int kA = ks * 16 + ((lane >> 4) << 3);
            const int kB = ks * 16 + (((lane >> 3) & 1) << 3);
#pragma unroll
            for (int i = 0; i < 4; ++i)
                ldmx4(a[i], sa +
                      (uint32_t)((wm + i * 16 + (lane & 15)) * STRD + kA) * 2);
#pragma unroll
            for (int j2 = 0; j2 < 2; ++j2)
                ldmx4(b[j2], sb +
                      (uint32_t)((wn + j2 * 16 + (lane & 7) + ((lane >> 4) << 3))
                                 * STRD + kB) * 2);
#pragma unroll
            for (int i = 0; i < 4; ++i)
#pragma unroll
                for (int j = 0; j < 4; ++j)
                    mma_bf16(acc[i][j], a[i], b[j >> 1][(j & 1) * 2],
                             b[j >> 1][(j & 1) * 2 + 1]);
        }

        if (ch + 4 < 16)
            mm_issue(A, B, As, Bs, (ch + 4) % NSTAGE, (ch + 4) * BK,
                     colbase, r0, c8);
        cp_commit();  // always commit (possibly empty) to keep group accounting
    }

    const int mrow = wm + (lane >> 2);
    const int ncol = colbase + wn + 2 * (lane & 3);

    if (mode == 2) {
        // add bias in place
#pragma unroll
        for (int i = 0; i < 4; ++i) {
            float b0 = bias[mrow + i * 16], b1 = bias[mrow + i * 16 + 8];
#pragma unroll
            for (int j = 0; j < 4; ++j) {
                acc[i][j][0] += b0; acc[i][j][1] += b0;
                acc[i][j][2] += b1; acc[i][j][3] += b1;
            }
        }
        // per-column softmax over this warp's 64 rows (one head).
        // Column (j,q) values: acc[i][j][q] (rows mrow+16i), acc[i][j][q+2]
        // (rows mrow+16i+8); other rows live at lanes lane^{4,8,16}.
#pragma unroll
        for (int j = 0; j < 4; ++j)
#pragma unroll
            for (int q = 0; q < 2; ++q) {
                float mx = -1e30f;
#pragma unroll
                for (int i = 0; i < 4; ++i)
                    mx = fmaxf(mx, fmaxf(acc[i][j][q], acc[i][j][q + 2]));
                mx = fmaxf(mx, __shfl_xor_sync(0xffffffffu, mx, 4));
                mx = fmaxf(mx, __shfl_xor_sync(0xffffffffu, mx, 8));
                mx = fmaxf(mx, __shfl_xor_sync(0xffffffffu, mx, 16));
                float s = 0.f;
#pragma unroll
                for (int i = 0; i < 4; ++i) {
                    acc[i][j][q]     = __expf(acc[i][j][q] - mx);
                    acc[i][j][q + 2] = __expf(acc[i][j][q + 2] - mx);
                    s += acc[i][j][q] + acc[i][j][q + 2];
                }
                s += __shfl_xor_sync(0xffffffffu, s, 4);
                s += __shfl_xor_sync(0xffffffffu, s, 8);
                s += __shfl_xor_sync(0xffffffffu, s, 16);
                float inv = 1.f / s;
#pragma unroll
                for (int i = 0; i < 4; ++i) {
                    acc[i][j][q] *= inv; acc[i][j][q + 2] *= inv;
                }
            }
    }

    // epilogue writes
#pragma unroll
    for (int i = 0; i < 4; ++i) {
        int m0 = mrow + i * 16;
        float b0 = (mode == 2) ? 0.f : bias[m0];
        float b1 = (mode == 2) ? 0.f : bias[m0 + 8];
#pragma unroll
        for (int j = 0; j < 4; ++j) {
            int n = ncol + j * 8;
            float* c = acc[i][j];
            if (mode != 0) {
                bf16* o = (bf16*)outp;
                *(__nv_bfloat162*)(o + (size_t)m0 * WW + n) =
                    __floats2bfloat162_rn(c[0] + b0, c[1] + b0);
                *(__nv_bfloat162*)(o + (size_t)(m0 + 8) * WW + n) =
                    __floats2bfloat162_rn(c[2] + b1, c[3] + b1);
            } else {
                float* o = (float*)outp;
                float2 r0v = *(const float2*)(resid + (size_t)m0 * WW + n);
                float2 r1v = *(const float2*)(resid + (size_t)(m0 + 8) * WW + n);
                float2 o0 = { c[0] + b0 + r0v.x, c[1] + b0 + r0v.y };
                float2 o1 = { c[2] + b1 + r1v.x, c[3] + b1 + r1v.y };
                *(float2*)(o + (size_t)m0 * WW + n) = o0;
                *(float2*)(o + (size_t)(m0 + 8) * WW + n) = o1;
            }
        }
    }
}

// ---------------------------------------------------------------------------
// conversions / init (first convw call also zeroes g_rows)
// ---------------------------------------------------------------------------
__global__ void __launch_bounds__(256)
k_convw(const float* __restrict__ s, bf16* __restrict__ d, int zero_rows)
{
    int gid = blockIdx.x * 256 + threadIdx.x;
    if (zero_rows && gid < NB * CC) g_rows[gid] = 0.f;
    int i = gid * 4;
    float4 v = *(const float4*)(s + i);
    __nv_bfloat162 o[2];
    o[0] = __floats2bfloat162_rn(v.x, v.y);
    o[1] = __floats2bfloat162_rn(v.z, v.w);
    *(uint2*)(d + i) = *(uint2*)o;
}

// 64x64 transpose tiles: 128B-coalesced reads and (bf16x2-packed) writes
__global__ void __launch_bounds__(256)
k_convx(const float* __restrict__ x)
{
    __shared__ float tile[64][65];
    int n = blockIdx.z, c0 = blockIdx.y * 64, w0 = blockIdx.x * 64;
    int t = threadIdx.x;
    int tx = t & 63, ty = t >> 6;            // read: 64 w per row, 4 rows/pass
    const float* xb = x + (size_t)n * CC * WW;
#pragma unroll
    for (int i = ty; i < 64; i += 4)
        tile[i][tx] = xb[(size_t)(c0 + i) * WW + w0 + tx];
    __syncthreads();
    bf16* ob = g_xt + (size_t)n * WW * CC;
    int cpair = (t & 31) * 2, wr = t >> 5;   // write: 32 c-pairs, 8 rows/pass
#pragma unroll
    for (int i = wr; i < 64; i += 8) {
        __nv_bfloat162 v = __floats2bfloat162_rn(tile[cpair][i], tile[cpair + 1][i]);
        *(__nv_bfloat162*)(ob + (size_t)(w0 + i) * CC + c0 + cpair) = v;
    }
}

// bf16 64x64 transpose: g_querb [n][c][w] -> g_sqt [n][w][c]
__global__ void __launch_bounds__(256) k_trq()
{
    __shared__ bf16 tile[64][72];
    int n = blockIdx.z, c0 = blockIdx.y * 64, w0 = blockIdx.x * 64;
    int t = threadIdx.x;
    int lr = t >> 2, ls = (t & 3) * 16;      // load: 4 threads/row, 16 w each
    const bf16* src = g_querb + (size_t)(n * CC + c0 + lr) * WW + w0 + ls;
    *(uint4*)&tile[lr][ls]     = *(const uint4*)src;
    *(uint4*)&tile[lr][ls + 8] = *(const uint4*)(src + 8);
    __syncthreads();
    int wr = t >> 2, cs = (t & 3) * 16;      // store: 4 threads/row, 16 c each
    bf16 buf[16];
#pragma unroll
    for (int i = 0; i < 16; ++i) buf[i] = tile[cs + i][wr];
    bf16* dst = g_sqt + ((size_t)n * WW + w0 + wr) * CC + c0 + cs;
    *(uint4*)dst       = *(uint4*)&buf[0];
    *(uint4*)(dst + 8) = *(uint4*)&buf[8];
}

// ---------------------------------------------------------------------------
// GEMM wrappers
// ---------------------------------------------------------------------------
__global__ void __launch_bounds__(256, 2)
k_proj(const float* __restrict__ bk, const float* __restrict__ bq,
       const float* __restrict__ bv)
{
    int mtile = blockIdx.y;
    int sect = mtile >> 2;
    int mbrow = (mtile & 3) * 128;
    int n = blockIdx.z;
    const bf16* A = g_wb + (size_t)sect * CC * CC + (size_t)mbrow * CC;
    const bf16* B = g_xt + (size_t)n * WW * CC;
    const float* bias = (sect == 0 ? bk : sect == 1 ? bq : bv) + mbrow;
    bf16* out = (sect == 0 ? g_keysb : sect == 1 ? g_querb : g_valsb)
                + (size_t)n * CC * WW + (size_t)mbrow * WW;
    mm_body(A, B, bias, nullptr, out, sect == 1 ? 2 : 1);
}

__global__ void __launch_bounds__(256, 2)
k_out(const float* __restrict__ x, const float* __restrict__ br,
      float* __restrict__ out)
{
    int mbrow = blockIdx.y * 128;
    int n = blockIdx.z;
    const bf16* A = g_Mb + (size_t)n * CC * CC + (size_t)mbrow * CC;
    const bf16* B = g_sqt + (size_t)n * WW * CC;
    const float* resid = x + (size_t)n * CC * WW + (size_t)mbrow * WW;
    float* O = out + (size_t)n * CC * WW + (size_t)mbrow * WW;
    mm_body(A, B, br + mbrow, resid, O, 0);
}

// ---------------------------------------------------------------------------
// ctx partials via HMMA: exp(K) @ V^T over 1024-wide w chunks, fused row sums.
// grid (64 nh, 8 chunks), 256 threads. smem [64][72] bf16, double-buffered.
// ---------------------------------------------------------------------------
#define CSTRD 72

__global__ void __launch_bounds__(256) k_ctx()
{
    __shared__ bf16 Ks[2][64 * CSTRD];
    __shared__ bf16 Vs[2][64 * CSTRD];

    int nh = blockIdx.x, chunk = blockIdx.y, t = threadIdx.x;
    int lane = t & 31, wid = t >> 5;
    int rowbase = nh * 64;
    int wbase = chunk * 1024;
    int lr = t >> 2;                 // 0..63 load row
    int seg = (t & 3) * 16;          // 0,16,32,48 (16 bf16 per thread)
    const bf16* kg = g_keysb + (size_t)(rowbase + lr) * WW + wbase + seg;
    const bf16* vg = g_valsb + (size_t)(rowbase + lr) * WW + wbase + seg;

    int wm = (wid & 3) * 16;         // warp out rows
    int wn = (wid >> 2) * 32;        // warp out cols

    float acc[4][4] = {};            // [n-chunk of 8][c0..c3]
    float srow = 0.f;

    uint4 kr[2], vr[2];
    kr[0] = *(const uint4*)kg;       kr[1] = *(const uint4*)(kg + 8);
    vr[0] = *(const uint4*)vg;       vr[1] = *(const uint4*)(vg + 8);

    for (int s = 0; s < 16; ++s) {
        const int b = s & 1;
        // exp(K) -> bf16 + STS; V STS
        uint4 ke[2];
#pragma unroll
        for (int u = 0; u < 2; ++u) {
            const __nv_bfloat162* kh = (const __nv_bfloat162*)&kr[u];
            __nv_bfloat162* eo = (__nv_bfloat162*)&ke[u];
#pragma unroll
            for (int i = 0; i < 4; ++i) {
                float2 f = __bfloat1622float2(kh[i]);
                float e0 = __expf(f.x), e1 = __expf(f.y);
                srow += e0 + e1;
                eo[i] = __floats2bfloat162_rn(e0, e1);
            }
        }
        bf16* kst = &Ks[b][lr * CSTRD + seg];
        bf16* vst = &Vs[b][lr * CSTRD + seg];
        *(uint4*)kst = ke[0];        *(uint4*)(kst + 8) = ke[1];
        *(uint4*)vst = vr[0];        *(uint4*)(vst + 8) = vr[1];
        __syncthreads();
        if (s < 15) {                 // prefetch next slice (hidden under mma)
            const bf16* kg2 = kg + (s + 1) * 64;
            const bf16* vg2 = vg + (s + 1) * 64;
            kr[0] = *(const uint4*)kg2; kr[1] = *(const uint4*)(kg2 + 8);
            vr[0] = *(const uint4*)vg2; vr[1] = *(const uint4*)(vg2 + 8);
        }
        const uint32_t sk = smem_u32(&Ks[b][0]);
        const uint32_t sv = smem_u32(&Vs[b][0]);
#pragma unroll
        for (int ks = 0; ks < 4; ++ks) {
            uint32_t a[4], bb[2][4];
            const int kA = ks * 16 + ((lane >> 4) << 3);
            const int kB = ks * 16 + (((lane >> 3) & 1) << 3);
            ldmx4(a, sk + (uint32_t)((wm + (lane & 15)) * CSTRD + kA) * 2);
#pragma unroll
            for (int j2 = 0; j2 < 2; ++j2)
                ldmx4(bb[j2], sv +
                      (uint32_t)((wn + j2 * 16 + (lane & 7) + ((lane >> 4) << 3))
                                 * CSTRD + kB) * 2);
#pragma unroll
            for (int j = 0; j < 4; ++j)
                mma_bf16(acc[j], a, bb[j >> 1][(j & 1) * 2],
                         bb[j >> 1][(j & 1) * 2 + 1]);
        }
        // no trailing sync: double buffer; next iteration's sync protects reuse
    }

    // fused row sums: 4 loader threads per row
    srow += __shfl_xor_sync(0xffffffffu, srow, 1);
    srow += __shfl_xor_sync(0xffffffffu, srow, 2);
    if ((t & 3) == 0) atomicAdd(&g_rows[rowbase + lr], srow);

    float* op = g_ctxp + (size_t)(nh * 8 + chunk) * 4096;
    int r0 = wm + (lane >> 2);
    int c0 = wn + (lane & 3) * 2;
#pragma unroll
    for (int j = 0; j < 4; ++j) {
        int c = c0 + j * 8;
        op[r0 * 64 + c]           = acc[j][0];
        op[r0 * 64 + c + 1]       = acc[j][1];
        op[(r0 + 8) * 64 + c]     = acc[j][2];
        op[(r0 + 8) * 64 + c + 1] = acc[j][3];
    }
}

// ---------------------------------------------------------------------------
// M[n][c][h*64+k] = sum_v Wr[c][h*64+v] * ctx[n][h][k][v]  (bf16 out)
// ctx partial reduction + 1/rowsum fused here (ctxp is L2-resident).
// ---------------------------------------------------------------------------
__global__ void __launch_bounds__(256) k_M(const float* __restrict__ Wr)
{
    int ct = blockIdx.x, h = blockIdx.y, n = blockIdx.z;
    __shared__ float Ws[64][65];
    __shared__ float Cs[64][65];
    int t = threadIdx.x;
    int nh = n * 8 + h;

    for (int e = t; e < 4096; e += 256) {
        int r = e >> 6, c = e & 63;
        Ws[r][c] = Wr[(size_t)(ct * 64 + r) * 512 + h * 64 + c];
        float sum = 0.f;
#pragma unroll
        for (int ch = 0; ch < 8; ++ch)
            sum += g_ctxp[(size_t)(nh * 8 + ch) * 4096 + e];
        Cs[r][c] = sum / g_rows[nh * 64 + r];
    }
    __syncthreads();

    int c0 = (t >> 4) << 2;
    int k0 = (t & 15) << 2;
    float acc[4][4] = {};
    for (int v = 0; v < 64; ++v) {
        float a_[4], b_[4];
#pragma unroll
        for (int i = 0; i < 4; ++i) a_[i] = Ws[c0 + i][v];
#pragma unroll
        for (int j = 0; j < 4; ++j) b_[j] = Cs[k0 + j][v];
#pragma unroll
        for (int i = 0; i < 4; ++i)
#pragma unroll
            for (int j = 0; j < 4; ++j)
                acc[i][j] = fmaf(a_[i], b_[j], acc[i][j]);
    }
#pragma unroll
    for (int i = 0; i < 4; ++i)
#pragma unroll
        for (int j = 0; j < 4; ++j)
            g_Mb[(size_t)n * 262144 + (size_t)(ct * 64 + c0 + i) * 512 + h * 64 + k0 + j]
                = __float2bfloat16(acc[i][j]);
}

// ---------------------------------------------------------------------------
extern "C" void kernel_launch(void* const* d_in, const int* in_sizes, int n_in,
                              void* d_out, int out_size)
{
    const float* x  = (const float*)d_in[0];
    const float* Wk = (const float*)d_in[1];
    const float* bk = (const float*)d_in[2];
    const float* Wq = (const float*)d_in[3];
    const float* bq = (const float*)d_in[4];
    const float* Wv = (const float*)d_in[5];
    const float* bv = (const float*)d_in[6];
    const float* Wr = (const float*)d_in[7];
    const float* br = (const float*)d_in[8];
    float* out = (float*)d_out;

    bf16* wb;
    cudaGetSymbolAddress((void**)&wb, g_wb);

    cudaFuncSetAttribute(k_proj, cudaFuncAttributeMaxDynamicSharedMemorySize, SMEMSZ);
    cudaFuncSetAttribute(k_out,  cudaFuncAttributeMaxDynamicSharedMemorySize, SMEMSZ);

    k_convw<<<256, 256>>>(Wk, wb, 1);
    k_convw<<<256, 256>>>(Wq, wb + 262144, 0);
    k_convw<<<256, 256>>>(Wv, wb + 524288, 0);
    k_convx<<<dim3(128, 8, 8), 256>>>(x);
    k_proj<<<dim3(64, 12, 8), 256, SMEMSZ>>>(bk, bq, bv);
    k_ctx<<<dim3(64, 8), 256>>>();
    k_M<<<dim3(8, 8, 8), 256>>>(Wr);
    k_trq<<<dim3(128, 8, 8), 256>>>();
    k_out<<<dim3(64, 4, 8), 256, SMEMSZ>>>(x, br, out);
}

// round 9
// speedup vs baseline: 5.1898x; 1.0404x over previous
#include <cuda_runtime.h>
#include <cuda_bf16.h>
#include <cstdint>
#include <cstddef>

#define NB 8
#define CC 512
#define WW 8192
#define HH 8

typedef __nv_bfloat16 bf16;

// ---------------- scratch (device globals; allocation-free) ----------------
__device__ bf16  g_xt  [(size_t)NB * WW * CC];   // x transposed [n][w][c] bf16
__device__ bf16  g_wb  [3 * CC * CC];            // Wk,Wq,Wv bf16
__device__ bf16  g_keysb[(size_t)NB * CC * WW];  // keys [n][c][w] bf16
__device__ bf16  g_valsb[(size_t)NB * CC * WW];  // values
__device__ bf16  g_sqt [(size_t)NB * WW * CC];   // softmax(Q) transposed [n][w][c]
__device__ bf16  g_Mb  [(size_t)NB * CC * CC];   // folded Wr@ctx^T (bf16)
__device__ float g_rows[NB * CC];                // sum(exp(keys)) per row
__device__ float g_ctxp[64 * 8 * 64 * 64];       // ctx partials

// ---------------- helpers (arch-neutral: ldmatrix / mma.sync / cp.async) ----
__device__ __forceinline__ uint32_t smem_u32(const void* p) {
    uint32_t a;
    asm("{ .reg .u64 t; cvta.to.shared.u64 t, %1; cvt.u32.u64 %0, t; }"
        : "=r"(a) : "l"(p));
    return a;
}
__device__ __forceinline__ void ldmx4(uint32_t* r, uint32_t addr) {
    asm volatile("ldmatrix.sync.aligned.m8n8.x4.shared.b16 {%0,%1,%2,%3}, [%4];"
                 : "=r"(r[0]), "=r"(r[1]), "=r"(r[2]), "=r"(r[3]) : "r"(addr));
}
__device__ __forceinline__ void mma_bf16(float* c, const uint32_t* a,
                                         const uint32_t b0, const uint32_t b1) {
    asm volatile(
        "mma.sync.aligned.m16n8k16.row.col.f32.bf16.bf16.f32 "
        "{%0,%1,%2,%3}, {%4,%5,%6,%7}, {%8,%9}, {%0,%1,%2,%3};"
        : "+f"(c[0]), "+f"(c[1]), "+f"(c[2]), "+f"(c[3])
        : "r"(a[0]), "r"(a[1]), "r"(a[2]), "r"(a[3]), "r"(b0), "r"(b1));
}
__device__ __forceinline__ void cp16(uint32_t dst, const void* src) {
    asm volatile("cp.async.cg.shared.global [%0], [%1], 16;" :: "r"(dst), "l"(src));
}
__device__ __forceinline__ void cp_commit() {
    asm volatile("cp.async.commit_group;");
}
template <int N>
__device__ __forceinline__ void cp_wait() {
    asm volatile("cp.async.wait_group %0;" :: "n"(N));
}

// ---------------------------------------------------------------------------
// HMMA GEMM body: D[256 x 128] = A[256 x 512] * B[colbase..+128, 512]^T
// bf16 K-major row-major operands. 512 threads, 16 warps (warp tile 64x32),
// 4-stage cp.async pipeline, BK=32.
// mode: 0 = fp32 out + residual; 1 = bf16 out;
//       2 = bf16 + per-head column softmax + transposed write to g_sqt
// ---------------------------------------------------------------------------
#define BK 32
#define STRD 40                      // smem row stride (80 B; ldmatrix conflict-free)
#define NSTAGE 4
#define A_ELEMS (256 * STRD)
#define B_ELEMS (128 * STRD)
#define SMEMSZ (NSTAGE * (A_ELEMS + B_ELEMS) * 2)   // 122880 B
#define TSTR 264                     // transposed Q tile row stride (elements)

__device__ __forceinline__ void mm_issue(
    const bf16* __restrict__ A, const bf16* __restrict__ B,
    bf16* As, bf16* Bs, int stage, int k0, int colbase, int tid)
{
    uint32_t sa = smem_u32(As + (size_t)stage * A_ELEMS);
    uint32_t sb = smem_u32(Bs + (size_t)stage * B_ELEMS);
#pragma unroll
    for (int p = 0; p < 2; ++p) {
        int idx = tid + p * 512;
        int row = idx >> 2;                  // 0..255
        int seg = (idx & 3) << 3;            // 0,8,16,24
        cp16(sa + (uint32_t)(row * STRD + seg) * 2,
             A + (size_t)row * 512 + k0 + seg);
    }
    int rb = tid >> 2;                       // 0..127
    int segb = (tid & 3) << 3;
    cp16(sb + (uint32_t)(rb * STRD + segb) * 2,
         B + (size_t)(colbase + rb) * 512 + k0 + segb);
}

__device__ __forceinline__ void mm_body(
    const bf16* __restrict__ A,          // pre-offset to its 256-row slab
    const bf16* __restrict__ B,          // [8192 x 512] per-batch slab
    const float* __restrict__ bias,      // pre-offset [256]
    const float* __restrict__ resid,     // pre-offset rows (or nullptr)
    void* __restrict__ outp,             // pre-offset (mode2: g_sqt + n slab + mbrow)
    int mode)
{
    extern __shared__ bf16 dsm[];
    bf16* As = dsm;
    bf16* Bs = dsm + (size_t)NSTAGE * A_ELEMS;

    const int tid = threadIdx.x;
    const int lane = tid & 31;
    const int wid = tid >> 5;                // 0..15
    const int wm = (wid & 3) * 64;           // warp M base (0..192)
    const int wn = (wid >> 2) * 32;          // warp N base (0..96)
    const int colbase = blockIdx.x * 128;

    float acc[4][4][4] = {};

    // prologue: stages 0..2
#pragma unroll
    for (int s = 0; s < 3; ++s) {
        mm_issue(A, B, As, Bs, s, s * BK, colbase, tid);
        cp_commit();
    }

    for (int ch = 0; ch < 16; ++ch) {
        cp_wait<2>();
        __syncthreads();
        const int cur = ch % NSTAGE;
        const uint32_t sa = smem_u32(As + (size_t)cur * A_ELEMS);
        const uint32_t sb = smem_u32(Bs + (size_t)cur * B_ELEMS);

#pragma unroll
        for (int ks = 0; ks < 2; ++ks) {
            uint32_t a[4][4], b[2][4];
            const int kA = ks * 16 + ((lane >> 4) << 3);
            const int kB = ks * 16 + (((lane >> 3) & 1) << 3);
#pragma unroll
            for (int i = 0; i < 4; ++i)
                ldmx4(a[i], sa +
                      (uint32_t)((wm + i * 16 + (lane & 15)) * STRD + kA) * 2);
#pragma unroll
            for (int j2 = 0; j2 < 2; ++j2)
                ldmx4(b[j2], sb +
                      (uint32_t)((wn + j2 * 16 + (lane & 7) + ((lane >> 4) << 3))
                                 * STRD + kB) * 2);
#pragma unroll
            for (int i = 0; i < 4; ++i)
#pragma unroll
                for (int j = 0; j < 4; ++j)
                    mma_bf16(acc[i][j], a[i], b[j >> 1][(j & 1) * 2],
                             b[j >> 1][(j & 1) * 2 + 1]);
        }

        if (ch + 3 < 16)
            mm_issue(A, B, As, Bs, (ch + 3) % NSTAGE, (ch + 3) * BK,
                     colbase, tid);
        cp_commit();  // always commit (possibly empty) to keep group accounting
    }

    const int mrow = wm + (lane >> 2);
    const int ncol = wn + 2 * (lane & 3);

    if (mode == 2) {
        // bias in place
#pragma unroll
        for (int i = 0; i < 4; ++i) {
            float b0 = bias[mrow + i * 16], b1 = bias[mrow + i * 16 + 8];
#pragma unroll
            for (int j = 0; j < 4; ++j) {
                acc[i][j][0] += b0; acc[i][j][1] += b0;
                acc[i][j][2] += b1; acc[i][j][3] += b1;
            }
        }
        // per-column softmax over this warp's 64 rows (exactly one head)
#pragma unroll
        for (int j = 0; j < 4; ++j)
#pragma unroll
            for (int q = 0; q < 2; ++q) {
                float mx = -1e30f;
#pragma unroll
                for (int i = 0; i < 4; ++i)
                    mx = fmaxf(mx, fmaxf(acc[i][j][q], acc[i][j][q + 2]));
                mx = fmaxf(mx, __shfl_xor_sync(0xffffffffu, mx, 4));
                mx = fmaxf(mx, __shfl_xor_sync(0xffffffffu, mx, 8));
                mx = fmaxf(mx, __shfl_xor_sync(0xffffffffu, mx, 16));
                float s = 0.f;
#pragma unroll
                for (int i = 0; i < 4; ++i) {
                    acc[i][j][q]     = __expf(acc[i][j][q] - mx);
                    acc[i][j][q + 2] = __expf(acc[i][j][q + 2] - mx);
                    s += acc[i][j][q] + acc[i][j][q + 2];
                }
                s += __shfl_xor_sync(0xffffffffu, s, 4);
                s += __shfl_xor_sync(0xffffffffu, s, 8);
                s += __shfl_xor_sync(0xffffffffu, s, 16);
                float inv = 1.f / s;
#pragma unroll
                for (int i = 0; i < 4; ++i) {
                    acc[i][j][q] *= inv; acc[i][j][q + 2] *= inv;
                }
            }
        // transpose through smem (pipeline buffers are dead now)
        __syncthreads();
        bf16* tile = dsm;                    // [128 w][TSTR] channels
#pragma unroll
        for (int i = 0; i < 4; ++i) {
            int m0 = mrow + i * 16;
#pragma unroll
            for (int j = 0; j < 4; ++j) {
                int nb = ncol + j * 8;
                float* c = acc[i][j];
                tile[(size_t)nb * TSTR + m0]           = __float2bfloat16(c[0]);
                tile[(size_t)(nb + 1) * TSTR + m0]     = __float2bfloat16(c[1]);
                tile[(size_t)nb * TSTR + m0 + 8]       = __float2bfloat16(c[2]);
                tile[(size_t)(nb + 1) * TSTR + m0 + 8] = __float2bfloat16(c[3]);
            }
        }
        __syncthreads();
        // coalesced store: g_sqt[(colbase+w)*CC + mbrow + c]
        bf16* oq = (bf16*)outp;
#pragma unroll
        for (int p = 0; p < 8; ++p) {
            int idx = tid + p * 512;
            int nl = idx >> 5;               // 0..127
            int seg = (idx & 31) * 8;        // 0..248
            *(uint4*)(oq + (size_t)(colbase + nl) * CC + seg) =
                *(uint4*)&tile[(size_t)nl * TSTR + seg];
        }
        return;
    }

    // regular epilogue
    const int ncolg = colbase + ncol;
#pragma unroll
    for (int i = 0; i < 4; ++i) {
        int m0 = mrow + i * 16;
        float b0 = bias[m0];
        float b1 = bias[m0 + 8];
#pragma unroll
        for (int j = 0; j < 4; ++j) {
            int n = ncolg + j * 8;
            float* c = acc[i][j];
            if (mode == 1) {
                bf16* o = (bf16*)outp;
                *(__nv_bfloat162*)(o + (size_t)m0 * WW + n) =
                    __floats2bfloat162_rn(c[0] + b0, c[1] + b0);
                *(__nv_bfloat162*)(o + (size_t)(m0 + 8) * WW + n) =
                    __floats2bfloat162_rn(c[2] + b1, c[3] + b1);
            } else {
                float* o = (float*)outp;
                float2 r0v = *(const float2*)(resid + (size_t)m0 * WW + n);
                float2 r1v = *(const float2*)(resid + (size_t)(m0 + 8) * WW + n);
                float2 o0 = { c[0] + b0 + r0v.x, c[1] + b0 + r0v.y };
                float2 o1 = { c[2] + b1 + r1v.x, c[3] + b1 + r1v.y };
                *(float2*)(o + (size_t)m0 * WW + n) = o0;
                *(float2*)(o + (size_t)(m0 + 8) * WW + n) = o1;
            }
        }
    }
}

// ---------------------------------------------------------------------------
// conversions / init (first convw call also zeroes g_rows)
// ---------------------------------------------------------------------------
__global__ void __launch_bounds__(256)
k_convw(const float* __restrict__ s, bf16* __restrict__ d, int zero_rows)
{
    int gid = blockIdx.x * 256 + threadIdx.x;
    if (zero_rows && gid < NB * CC) g_rows[gid] = 0.f;
    int i = gid * 4;
    float4 v = *(const float4*)(s + i);
    __nv_bfloat162 o[2];
    o[0] = __floats2bfloat162_rn(v.x, v.y);
    o[1] = __floats2bfloat162_rn(v.z, v.w);
    *(uint2*)(d + i) = *(uint2*)o;
}

// 64x64 transpose tiles: 128B-coalesced reads and (bf16x2-packed) writes
__global__ void __launch_bounds__(256)
k_convx(const float* __restrict__ x)
{
    __shared__ float tile[64][65];
    int n = blockIdx.z, c0 = blockIdx.y * 64, w0 = blockIdx.x * 64;
    int t = threadIdx.x;
    int tx = t & 63, ty = t >> 6;            // read: 64 w per row, 4 rows/pass
    const float* xb = x + (size_t)n * CC * WW;
#pragma unroll
    for (int i = ty; i < 64; i += 4)
        tile[i][tx] = xb[(size_t)(c0 + i) * WW + w0 + tx];
    __syncthreads();
    bf16* ob = g_xt + (size_t)n * WW * CC;
    int cpair = (t & 31) * 2, wr = t >> 5;   // write: 32 c-pairs, 8 rows/pass
#pragma unroll
    for (int i = wr; i < 64; i += 8) {
        __nv_bfloat162 v = __floats2bfloat162_rn(tile[cpair][i], tile[cpair + 1][i]);
        *(__nv_bfloat162*)(ob + (size_t)(w0 + i) * CC + c0 + cpair) = v;
    }
}

// ---------------------------------------------------------------------------
// GEMM wrappers
// ---------------------------------------------------------------------------
__global__ void __launch_bounds__(512, 1)
k_proj(const float* __restrict__ bk, const float* __restrict__ bq,
       const float* __restrict__ bv)
{
    int mtile = blockIdx.y;                  // 0..5
    int sect = mtile >> 1;                   // 0=K 1=Q 2=V
    int mbrow = (mtile & 1) * 256;
    int n = blockIdx.z;
    const bf16* A = g_wb + (size_t)sect * CC * CC + (size_t)mbrow * CC;
    const bf16* B = g_xt + (size_t)n * WW * CC;
    const float* bias = (sect == 0 ? bk : sect == 1 ? bq : bv) + mbrow;
    if (sect == 1) {
        bf16* out = g_sqt + (size_t)n * WW * CC + mbrow;   // channel offset
        mm_body(A, B, bias, nullptr, out, 2);
    } else {
        bf16* out = (sect == 0 ? g_keysb : g_valsb)
                    + (size_t)n * CC * WW + (size_t)mbrow * WW;
        mm_body(A, B, bias, nullptr, out, 1);
    }
}

__global__ void __launch_bounds__(512, 1)
k_out(const float* __restrict__ x, const float* __restrict__ br,
      float* __restrict__ out)
{
    int mbrow = blockIdx.y * 256;
    int n = blockIdx.z;
    const bf16* A = g_Mb + (size_t)n * CC * CC + (size_t)mbrow * CC;
    const bf16* B = g_sqt + (size_t)n * WW * CC;
    const float* resid = x + (size_t)n * CC * WW + (size_t)mbrow * WW;
    float* O = out + (size_t)n * CC * WW + (size_t)mbrow * WW;
    mm_body(A, B, br + mbrow, resid, O, 0);
}

// ---------------------------------------------------------------------------
// ctx partials via HMMA: exp(K) @ V^T over 1024-wide w chunks, fused row sums.
// grid (64 nh, 8 chunks), 256 threads. smem [64][72] bf16, double-buffered.
// ---------------------------------------------------------------------------
#define CSTRD 72

__global__ void __launch_bounds__(256) k_ctx()
{
    __shared__ bf16 Ks[2][64 * CSTRD];
    __shared__ bf16 Vs[2][64 * CSTRD];

    int nh = blockIdx.x, chunk = blockIdx.y, t = threadIdx.x;
    int lane = t & 31, wid = t >> 5;
    int rowbase = nh * 64;
    int wbase = chunk * 1024;
    int lr = t >> 2;                 // 0..63 load row
    int seg = (t & 3) * 16;          // 0,16,32,48 (16 bf16 per thread)
    const bf16* kg = g_keysb + (size_t)(rowbase + lr) * WW + wbase + seg;
    const bf16* vg = g_valsb + (size_t)(rowbase + lr) * WW + wbase + seg;

    int wm = (wid & 3) * 16;         // warp out rows
    int wn = (wid >> 2) * 32;        // warp out cols

    float acc[4][4] = {};            // [n-chunk of 8][c0..c3]
    float srow = 0.f;

    uint4 kr[2], vr[2];
    kr[0] = *(const uint4*)kg;       kr[1] = *(const uint4*)(kg + 8);
    vr[0] = *(const uint4*)vg;       vr[1] = *(const uint4*)(vg + 8);

    for (int s = 0; s < 16; ++s) {
        const int b = s & 1;
        uint4 ke[2];
#pragma unroll
        for (int u = 0; u < 2; ++u) {
            const __nv_bfloat162* kh = (const __nv_bfloat162*)&kr[u];
            __nv_bfloat162* eo = (__nv_bfloat162*)&ke[u];
#pragma unroll
            for (int i = 0; i < 4; ++i) {
                float2 f = __bfloat1622float2(kh[i]);
                float e0 = __expf(f.x), e1 = __expf(f.y);
                srow += e0 + e1;
                eo[i] = __floats2bfloat162_rn(e0, e1);
            }
        }
        bf16* kst = &Ks[b][lr * CSTRD + seg];
        bf16* vst = &Vs[b][lr * CSTRD + seg];
        *(uint4*)kst = ke[0];        *(uint4*)(kst + 8) = ke[1];
        *(uint4*)vst = vr[0];        *(uint4*)(vst + 8) = vr[1];
        __syncthreads();
        if (s < 15) {                 // prefetch next slice (hidden under mma)
            const bf16* kg2 = kg + (s + 1) * 64;
            const bf16* vg2 = vg + (s + 1) * 64;
            kr[0] = *(const uint4*)kg2; kr[1] = *(const uint4*)(kg2 + 8);
            vr[0] = *(const uint4*)vg2; vr[1] = *(const uint4*)(vg2 + 8);
        }
        const uint32_t sk = smem_u32(&Ks[b][0]);
        const uint32_t sv = smem_u32(&Vs[b][0]);
#pragma unroll
        for (int ks = 0; ks < 4; ++ks) {
            uint32_t a[4], bb[2][4];
            const int kA = ks * 16 + ((lane >> 4) << 3);
            const int kB = ks * 16 + (((lane >> 3) & 1) << 3);
            ldmx4(a, sk + (uint32_t)((wm + (lane & 15)) * CSTRD + kA) * 2);
#pragma unroll
            for (int j2 = 0; j2 < 2; ++j2)
                ldmx4(bb[j2], sv +
                      (uint32_t)((wn + j2 * 16 + (lane & 7) + ((lane >> 4) << 3))
                                 * CSTRD + kB) * 2);
#pragma unroll
            for (int j = 0; j < 4; ++j)
                mma_bf16(acc[j], a, bb[j >> 1][(j & 1) * 2],
                         bb[j >> 1][(j & 1) * 2 + 1]);
        }
    }

    srow += __shfl_xor_sync(0xffffffffu, srow, 1);
    srow += __shfl_xor_sync(0xffffffffu, srow, 2);
    if ((t & 3) == 0) atomicAdd(&g_rows[rowbase + lr], srow);

    float* op = g_ctxp + (size_t)(nh * 8 + chunk) * 4096;
    int r0 = wm + (lane >> 2);
    int c0 = wn + (lane & 3) * 2;
#pragma unroll
    for (int j = 0; j < 4; ++j) {
        int c = c0 + j * 8;
        op[r0 * 64 + c]           = acc[j][0];
        op[r0 * 64 + c + 1]       = acc[j][1];
        op[(r0 + 8) * 64 + c]     = acc[j][2];
        op[(r0 + 8) * 64 + c + 1] = acc[j][3];
    }
}

// ---------------------------------------------------------------------------
// M[n][c][h*64+k] = sum_v Wr[c][h*64+v] * ctx[n][h][k][v]  (bf16 out)
// ctx partial reduction + 1/rowsum fused here (ctxp is L2-resident).
// ---------------------------------------------------------------------------
__global__ void __launch_bounds__(256) k_M(const float* __restrict__ Wr)
{
    int ct = blockIdx.x, h = blockIdx.y, n = blockIdx.z;
    __shared__ float Ws[64][65];
    __shared__ float Cs[64][65];
    int t = threadIdx.x;
    int nh = n * 8 + h;

    for (int e = t; e < 4096; e += 256) {
        int r = e >> 6, c = e & 63;
        Ws[r][c] = Wr[(size_t)(ct * 64 + r) * 512 + h * 64 + c];
        float sum = 0.f;
#pragma unroll
        for (int ch = 0; ch < 8; ++ch)
            sum += g_ctxp[(size_t)(nh * 8 + ch) * 4096 + e];
        Cs[r][c] = sum / g_rows[nh * 64 + r];
    }
    __syncthreads();

    int c0 = (t >> 4) << 2;
    int k0 = (t & 15) << 2;
    float acc[4][4] = {};
    for (int v = 0; v < 64; ++v) {
        float a_[4], b_[4];
#pragma unroll
        for (int i = 0; i < 4; ++i) a_[i] = Ws[c0 + i][v];
#pragma unroll
        for (int j = 0; j < 4; ++j) b_[j] = Cs[k0 + j][v];
#pragma unroll
        for (int i = 0; i < 4; ++i)
#pragma unroll
            for (int j = 0; j < 4; ++j)
                acc[i][j] = fmaf(a_[i], b_[j], acc[i][j]);
    }
#pragma unroll
    for (int i = 0; i < 4; ++i)
#pragma unroll
        for (int j = 0; j < 4; ++j)
            g_Mb[(size_t)n * 262144 + (size_t)(ct * 64 + c0 + i) * 512 + h * 64 + k0 + j]
                = __float2bfloat16(acc[i][j]);
}

// ---------------------------------------------------------------------------
extern "C" void kernel_launch(void* const* d_in, const int* in_sizes, int n_in,
                              void* d_out, int out_size)
{
    const float* x  = (const float*)d_in[0];
    const float* Wk = (const float*)d_in[1];
    const float* bk = (const float*)d_in[2];
    const float* Wq = (const float*)d_in[3];
    const float* bq = (const float*)d_in[4];
    const float* Wv = (const float*)d_in[5];
    const float* bv = (const float*)d_in[6];
    const float* Wr = (const float*)d_in[7];
    const float* br = (const float*)d_in[8];
    float* out = (float*)d_out;

    bf16* wb;
    cudaGetSymbolAddress((void**)&wb, g_wb);

    cudaFuncSetAttribute(k_proj, cudaFuncAttributeMaxDynamicSharedMemorySize, SMEMSZ);
    cudaFuncSetAttribute(k_out,  cudaFuncAttributeMaxDynamicSharedMemorySize, SMEMSZ);

    k_convw<<<256, 256>>>(Wk, wb, 1);
    k_convw<<<256, 256>>>(Wq, wb + 262144, 0);
    k_convw<<<256, 256>>>(Wv, wb + 524288, 0);
    k_convx<<<dim3(128, 8, 8), 256>>>(x);
    k_proj<<<dim3(64, 6, 8), 512, SMEMSZ>>>(bk, bq, bv);
    k_ctx<<<dim3(64, 8), 256>>>();
    k_M<<<dim3(8, 8, 8), 256>>>(Wr);
    k_out<<<dim3(64, 2, 8), 512, SMEMSZ>>>(x, br, out);
}

// round 11
// speedup vs baseline: 5.8201x; 1.1214x over previous
#include <cuda_runtime.h>
#include <cuda_bf16.h>
#include <cstdint>
#include <cstddef>

#define NB 8
#define CC 512
#define WW 8192
#define HH 8

typedef __nv_bfloat16 bf16;

// ---------------- scratch (device globals; allocation-free) ----------------
__device__ bf16  g_xt  [(size_t)NB * WW * CC];   // x transposed [n][w][c] bf16
__device__ bf16  g_wb  [3 * CC * CC];            // Wk,Wq,Wv bf16
__device__ bf16  g_keysb[(size_t)NB * CC * WW];  // keys [n][c][w] bf16
__device__ bf16  g_valsb[(size_t)NB * CC * WW];  // values
__device__ bf16  g_sqt [(size_t)NB * WW * CC];   // softmax(Q) transposed [n][w][c]
__device__ bf16  g_Mb  [(size_t)NB * CC * CC];   // folded Wr@ctx^T (bf16)
__device__ float g_rows[NB * CC];                // sum(exp(keys)) per row
__device__ float g_ctxp[64 * 8 * 64 * 64];       // ctx partials

// ---------------- helpers (arch-neutral: ldmatrix / mma.sync / cp.async) ----
__device__ __forceinline__ uint32_t smem_u32(const void* p) {
    uint32_t a;
    asm("{ .reg .u64 t; cvta.to.shared.u64 t, %1; cvt.u32.u64 %0, t; }"
        : "=r"(a) : "l"(p));
    return a;
}
__device__ __forceinline__ void ldmx4(uint32_t* r, uint32_t addr) {
    asm volatile("ldmatrix.sync.aligned.m8n8.x4.shared.b16 {%0,%1,%2,%3}, [%4];"
                 : "=r"(r[0]), "=r"(r[1]), "=r"(r[2]), "=r"(r[3]) : "r"(addr));
}
__device__ __forceinline__ void mma_bf16(float* c, const uint32_t* a,
                                         const uint32_t b0, const uint32_t b1) {
    asm volatile(
        "mma.sync.aligned.m16n8k16.row.col.f32.bf16.bf16.f32 "
        "{%0,%1,%2,%3}, {%4,%5,%6,%7}, {%8,%9}, {%0,%1,%2,%3};"
        : "+f"(c[0]), "+f"(c[1]), "+f"(c[2]), "+f"(c[3])
        : "r"(a[0]), "r"(a[1]), "r"(a[2]), "r"(a[3]), "r"(b0), "r"(b1));
}
__device__ __forceinline__ void cp16(uint32_t dst, const void* src) {
    asm volatile("cp.async.cg.shared.global [%0], [%1], 16;" :: "r"(dst), "l"(src));
}
__device__ __forceinline__ void cp_commit() {
    asm volatile("cp.async.commit_group;");
}
template <int N>
__device__ __forceinline__ void cp_wait() {
    asm volatile("cp.async.wait_group %0;" :: "n"(N));
}

// ---------------------------------------------------------------------------
// HMMA GEMM body: D[256 x 128] = A[256 x 512] * B[colbase..+128, 512]^T
// bf16 K-major row-major operands. 512 threads, 16 warps (warp tile 64x32),
// 5-stage cp.async pipeline, BK=32.
// mode: 0 = fp32 out + residual; 1 = bf16 out;
//       2 = bf16 + per-head column softmax + transposed write to g_sqt
// ---------------------------------------------------------------------------
#define BK 32
#define STRD 40                      // smem row stride (80 B; ldmatrix conflict-free)
#define NSTAGE 5
#define A_ELEMS (256 * STRD)
#define B_ELEMS (128 * STRD)
#define SMEMSZ (NSTAGE * (A_ELEMS + B_ELEMS) * 2)   // 153600 B
#define TSTR 264                     // transposed Q tile row stride (elements)

__device__ __forceinline__ void mm_issue(
    const bf16* __restrict__ A, const bf16* __restrict__ B,
    bf16* As, bf16* Bs, int stage, int k0, int colbase, int tid)
{
    uint32_t sa = smem_u32(As + (size_t)stage * A_ELEMS);
    uint32_t sb = smem_u32(Bs + (size_t)stage * B_ELEMS);
#pragma unroll
    for (int p = 0; p < 2; ++p) {
        int idx = tid + p * 512;
        int row = idx >> 2;                  // 0..255
        int seg = (idx & 3) << 3;            // 0,8,16,24
        cp16(sa + (uint32_t)(row * STRD + seg) * 2,
             A + (size_t)row * 512 + k0 + seg);
    }
    int rb = tid >> 2;                       // 0..127
    int segb = (tid & 3) << 3;
    cp16(sb + (uint32_t)(rb * STRD + segb) * 2,
         B + (size_t)(colbase + rb) * 512 + k0 + segb);
}

__device__ __forceinline__ void mm_body(
    const bf16* __restrict__ A,          // pre-offset to its 256-row slab
    const bf16* __restrict__ B,          // [8192 x 512] per-batch slab
    const float* __restrict__ bias,      // pre-offset [256]
    const float* __restrict__ resid,     // pre-offset rows (or nullptr)
    void* __restrict__ outp,             // pre-offset (mode2: g_sqt + n slab + mbrow)
    int mode)
{
    extern __shared__ bf16 dsm[];
    bf16* As = dsm;
    bf16* Bs = dsm + (size_t)NSTAGE * A_ELEMS;

    const int tid = threadIdx.x;
    const int lane = tid & 31;
    const int wid = tid >> 5;                // 0..15
    const int wm = (wid & 3) * 64;           // warp M base (0..192)
    const int wn = (wid >> 2) * 32;          // warp N base (0..96)
    const int colbase = blockIdx.x * 128;

    // hoisted per-warp ldmatrix offsets (element units, within a stage)
    const uint32_t aoff0 =
        (uint32_t)((wm + (lane & 15)) * STRD + ((lane >> 4) << 3));
    const uint32_t boffE[2] = {
        (uint32_t)((wn + (lane & 7) + ((lane >> 4) << 3)) * STRD
                   + (((lane >> 3) & 1) << 3)),
        (uint32_t)((wn + 16 + (lane & 7) + ((lane >> 4) << 3)) * STRD
                   + (((lane >> 3) & 1) << 3)) };

    float acc[4][4][4] = {};

    // prologue: stages 0..3
#pragma unroll
    for (int s = 0; s < 4; ++s) {
        mm_issue(A, B, As, Bs, s, s * BK, colbase, tid);
        cp_commit();
    }

    for (int ch = 0; ch < 16; ++ch) {
        cp_wait<3>();
        __syncthreads();
        const int cur = ch % NSTAGE;
        const uint32_t sa = smem_u32(As + (size_t)cur * A_ELEMS);
        const uint32_t sb = smem_u32(Bs + (size_t)cur * B_ELEMS);

#pragma unroll
        for (int ks = 0; ks < 2; ++ks) {
            uint32_t a[4][4], b[2][4];
            const uint32_t kk = (uint32_t)(ks * 16) * 2;
#pragma unroll
            for (int i = 0; i < 4; ++i)
                ldmx4(a[i], sa + (aoff0 + (uint32_t)(i * 16) * STRD) * 2 + kk);
#pragma unroll
            for (int j2 = 0; j2 < 2; ++j2)
                ldmx4(b[j2], sb + boffE[j2] * 2 + kk);
#pragma unroll
            for (int i = 0; i < 4; ++i)
#pragma unroll
                for (int j = 0; j < 4; ++j)
                    mma_bf16(acc[i][j], a[i], b[j >> 1][(j & 1) * 2],
                             b[j >> 1][(j & 1) * 2 + 1]);
        }

        if (ch + 4 < 16)
            mm_issue(A, B, As, Bs, (ch + 4) % NSTAGE, (ch + 4) * BK,
                     colbase, tid);
        cp_commit();  // always commit (possibly empty) to keep group accounting
    }

    const int mrow = wm + (lane >> 2);
    const int ncol = wn + 2 * (lane & 3);

    if (mode == 2) {
        // bias in place
#pragma unroll
        for (int i = 0; i < 4; ++i) {
            float b0 = bias[mrow + i * 16], b1 = bias[mrow + i * 16 + 8];
#pragma unroll
            for (int j = 0; j < 4; ++j) {
                acc[i][j][0] += b0; acc[i][j][1] += b0;
                acc[i][j][2] += b1; acc[i][j][3] += b1;
            }
        }
        // per-column softmax over this warp's 64 rows (exactly one head)
#pragma unroll
        for (int j = 0; j < 4; ++j)
#pragma unroll
            for (int q = 0; q < 2; ++q) {
                float mx = -1e30f;
#pragma unroll
                for (int i = 0; i < 4; ++i)
                    mx = fmaxf(mx, fmaxf(acc[i][j][q], acc[i][j][q + 2]));
                mx = fmaxf(mx, __shfl_xor_sync(0xffffffffu, mx, 4));
                mx = fmaxf(mx, __shfl_xor_sync(0xffffffffu, mx, 8));
                mx = fmaxf(mx, __shfl_xor_sync(0xffffffffu, mx, 16));
                float s = 0.f;
#pragma unroll
                for (int i = 0; i < 4; ++i) {
                    acc[i][j][q]     = __expf(acc[i][j][q] - mx);
                    acc[i][j][q + 2] = __expf(acc[i][j][q + 2] - mx);
                    s += acc[i][j][q] + acc[i][j][q + 2];
                }
                s += __shfl_xor_sync(0xffffffffu, s, 4);
                s += __shfl_xor_sync(0xffffffffu, s, 8);
                s += __shfl_xor_sync(0xffffffffu, s, 16);
                float inv = 1.f / s;
#pragma unroll
                for (int i = 0; i < 4; ++i) {
                    acc[i][j][q] *= inv; acc[i][j][q + 2] *= inv;
                }
            }
        // transpose through smem (pipeline buffers are dead now)
        __syncthreads();
        bf16* tile = dsm;                    // [128 w][TSTR] channels
#pragma unroll
        for (int i = 0; i < 4; ++i) {
            int m0 = mrow + i * 16;
#pragma unroll
            for (int j = 0; j < 4; ++j) {
                int nb = ncol + j * 8;
                float* c = acc[i][j];
                tile[(size_t)nb * TSTR + m0]           = __float2bfloat16(c[0]);
                tile[(size_t)(nb + 1) * TSTR + m0]     = __float2bfloat16(c[1]);
                tile[(size_t)nb * TSTR + m0 + 8]       = __float2bfloat16(c[2]);
                tile[(size_t)(nb + 1) * TSTR + m0 + 8] = __float2bfloat16(c[3]);
            }
        }
        __syncthreads();
        // coalesced store: g_sqt[(colbase+w)*CC + mbrow + c]
        bf16* oq = (bf16*)outp;
#pragma unroll
        for (int p = 0; p < 8; ++p) {
            int idx = tid + p * 512;
            int nl = idx >> 5;               // 0..127
            int seg = (idx & 31) * 8;        // 0..248
            *(uint4*)(oq + (size_t)(colbase + nl) * CC + seg) =
                *(uint4*)&tile[(size_t)nl * TSTR + seg];
        }
        return;
    }

    // regular epilogue
    const int ncolg = colbase + ncol;
#pragma unroll
    for (int i = 0; i < 4; ++i) {
        int m0 = mrow + i * 16;
        float b0 = bias[m0];
        float b1 = bias[m0 + 8];
#pragma unroll
        for (int j = 0; j < 4; ++j) {
            int n = ncolg + j * 8;
            float* c = acc[i][j];
            if (mode == 1) {
                bf16* o = (bf16*)outp;
                *(__nv_bfloat162*)(o + (size_t)m0 * WW + n) =
                    __floats2bfloat162_rn(c[0] + b0, c[1] + b0);
                *(__nv_bfloat162*)(o + (size_t)(m0 + 8) * WW + n) =
                    __floats2bfloat162_rn(c[2] + b1, c[3] + b1);
            } else {
                float* o = (float*)outp;
                float2 r0v = *(const float2*)(resid + (size_t)m0 * WW + n);
                float2 r1v = *(const float2*)(resid + (size_t)(m0 + 8) * WW + n);
                float2 o0 = { c[0] + b0 + r0v.x, c[1] + b0 + r0v.y };
                float2 o1 = { c[2] + b1 + r1v.x, c[3] + b1 + r1v.y };
                *(float2*)(o + (size_t)m0 * WW + n) = o0;
                *(float2*)(o + (size_t)(m0 + 8) * WW + n) = o1;
            }
        }
    }
}

// ---------------------------------------------------------------------------
// single conversion kernel: all 3 weights + zero g_rows
// ---------------------------------------------------------------------------
__global__ void __launch_bounds__(256)
k_convw_all(const float* __restrict__ Wk, const float* __restrict__ Wq,
            const float* __restrict__ Wv, bf16* __restrict__ d)
{
    int gid = blockIdx.x * 256 + threadIdx.x;          // 0..196607
    if (gid < NB * CC) g_rows[gid] = 0.f;
    int sect = gid >> 16;
    int local = gid & 65535;
    const float* s = (sect == 0 ? Wk : sect == 1 ? Wq : Wv);
    int i = local * 4;
    float4 v = *(const float4*)(s + i);
    __nv_bfloat162 o[2];
    o[0] = __floats2bfloat162_rn(v.x, v.y);
    o[1] = __floats2bfloat162_rn(v.z, v.w);
    *(uint2*)(d + (size_t)sect * 262144 + i) = *(uint2*)o;
}

// 64x64 transpose tiles: 128B-coalesced reads and (bf16x2-packed) writes
__global__ void __launch_bounds__(256)
k_convx(const float* __restrict__ x)
{
    __shared__ float tile[64][65];
    int n = blockIdx.z, c0 = blockIdx.y * 64, w0 = blockIdx.x * 64;
    int t = threadIdx.x;
    int tx = t & 63, ty = t >> 6;            // read: 64 w per row, 4 rows/pass
    const float* xb = x + (size_t)n * CC * WW;
#pragma unroll
    for (int i = ty; i < 64; i += 4)
        tile[i][tx] = xb[(size_t)(c0 + i) * WW + w0 + tx];
    __syncthreads();
    bf16* ob = g_xt + (size_t)n * WW * CC;
    int cpair = (t & 31) * 2, wr = t >> 5;   // write: 32 c-pairs, 8 rows/pass
#pragma unroll
    for (int i = wr; i < 64; i += 8) {
        __nv_bfloat162 v = __floats2bfloat162_rn(tile[cpair][i], tile[cpair + 1][i]);
        *(__nv_bfloat162*)(ob + (size_t)(w0 + i) * CC + c0 + cpair) = v;
    }
}

// ---------------------------------------------------------------------------
// GEMM wrappers
// ---------------------------------------------------------------------------
__global__ void __launch_bounds__(512, 1)
k_proj(const float* __restrict__ bk, const float* __restrict__ bq,
       const float* __restrict__ bv)
{
    int mtile = blockIdx.y;                  // 0..5
    int sect = mtile >> 1;                   // 0=K 1=Q 2=V
    int mbrow = (mtile & 1) * 256;
    int n = blockIdx.z;
    const bf16* A = g_wb + (size_t)sect * CC * CC + (size_t)mbrow * CC;
    const bf16* B = g_xt + (size_t)n * WW * CC;
    const float* bias = (sect == 0 ? bk : sect == 1 ? bq : bv) + mbrow;
    if (sect == 1) {
        bf16* out = g_sqt + (size_t)n * WW * CC + mbrow;   // channel offset
        mm_body(A, B, bias, nullptr, out, 2);
    } else {
        bf16* out = (sect == 0 ? g_keysb : g_valsb)
                    + (size_t)n * CC * WW + (size_t)mbrow * WW;
        mm_body(A, B, bias, nullptr, out, 1);
    }
}

__global__ void __launch_bounds__(512, 1)
k_out(const float* __restrict__ x, const float* __restrict__ br,
      float* __restrict__ out)
{
    int mbrow = blockIdx.y * 256;
    int n = blockIdx.z;
    const bf16* A = g_Mb + (size_t)n * CC * CC + (size_t)mbrow * CC;
    const bf16* B = g_sqt + (size_t)n * WW * CC;
    const float* resid = x + (size_t)n * CC * WW + (size_t)mbrow * WW;
    float* O = out + (size_t)n * CC * WW + (size_t)mbrow * WW;
    mm_body(A, B, br + mbrow, resid, O, 0);
}

// ---------------------------------------------------------------------------
// ctx partials via HMMA: exp(K) @ V^T over 1024-wide w chunks, fused row sums.
// grid (64 nh, 8 chunks), 256 threads. smem [64][72] bf16, double-buffered.
// ---------------------------------------------------------------------------
#define CSTRD 72

__global__ void __launch_bounds__(256) k_ctx()
{
    __shared__ bf16 Ks[2][64 * CSTRD];
    __shared__ bf16 Vs[2][64 * CSTRD];

    int nh = blockIdx.x, chunk = blockIdx.y, t = threadIdx.x;
    int lane = t & 31, wid = t >> 5;
    int rowbase = nh * 64;
    int wbase = chunk * 1024;
    int lr = t >> 2;                 // 0..63 load row
    int seg = (t & 3) * 16;          // 0,16,32,48 (16 bf16 per thread)
    const bf16* kg = g_keysb + (size_t)(rowbase + lr) * WW + wbase + seg;
    const bf16* vg = g_valsb + (size_t)(rowbase + lr) * WW + wbase + seg;

    int wm = (wid & 3) * 16;         // warp out rows
    int wn = (wid >> 2) * 32;        // warp out cols

    float acc[4][4] = {};            // [n-chunk of 8][c0..c3]
    float srow = 0.f;

    uint4 kr[2], vr[2];
    kr[0] = *(const uint4*)kg;       kr[1] = *(const uint4*)(kg + 8);
    vr[0] = *(const uint4*)vg;       vr[1] = *(const uint4*)(vg + 8);

    for (int s = 0; s < 16; ++s) {
        const int b = s & 1;
        uint4 ke[2];
#pragma unroll
        for (int u = 0; u < 2; ++u) {
            const __nv_bfloat162* kh = (const __nv_bfloat162*)&kr[u];
            __nv_bfloat162* eo = (__nv_bfloat162*)&ke[u];
#pragma unroll
            for (int i = 0; i < 4; ++i) {
                float2 f = __bfloat1622float2(kh[i]);
                float e0 = __expf(f.x), e1 = __expf(f.y);
                srow += e0 + e1;
                eo[i] = __floats2bfloat162_rn(e0, e1);
            }
        }
        bf16* kst = &Ks[b][lr * CSTRD + seg];
        bf16* vst = &Vs[b][lr * CSTRD + seg];
        *(uint4*)kst = ke[0];        *(uint4*)(kst + 8) = ke[1];
        *(uint4*)vst = vr[0];        *(uint4*)(vst + 8) = vr[1];
        __syncthreads();
        if (s < 15) {                 // prefetch next slice (hidden under mma)
            const bf16* kg2 = kg + (s + 1) * 64;
            const bf16* vg2 = vg + (s + 1) * 64;
            kr[0] = *(const uint4*)kg2; kr[1] = *(const uint4*)(kg2 + 8);
            vr[0] = *(const uint4*)vg2; vr[1] = *(const uint4*)(vg2 + 8);
        }
        const uint32_t sk = smem_u32(&Ks[b][0]);
        const uint32_t sv = smem_u32(&Vs[b][0]);
#pragma unroll
        for (int ks = 0; ks < 4; ++ks) {
            uint32_t a[4], bb[2][4];
            const int kA = ks * 16 + ((lane >> 4) << 3);
            const int kB = ks * 16 + (((lane >> 3) & 1) << 3);
            ldmx4(a, sk + (uint32_t)((wm + (lane & 15)) * CSTRD + kA) * 2);
#pragma unroll
            for (int j2 = 0; j2 < 2; ++j2)
                ldmx4(bb[j2], sv +
                      (uint32_t)((wn + j2 * 16 + (lane & 7) + ((lane >> 4) << 3))
                                 * CSTRD + kB) * 2);
#pragma unroll
            for (int j = 0; j < 4; ++j)
                mma_bf16(acc[j], a, bb[j >> 1][(j & 1) * 2],
                         bb[j >> 1][(j & 1) * 2 + 1]);
        }
    }

    srow += __shfl_xor_sync(0xffffffffu, srow, 1);
    srow += __shfl_xor_sync(0xffffffffu, srow, 2);
    if ((t & 3) == 0) atomicAdd(&g_rows[rowbase + lr], srow);

    float* op = g_ctxp + (size_t)(nh * 8 + chunk) * 4096;
    int r0 = wm + (lane >> 2);
    int c0 = wn + (lane & 3) * 2;
#pragma unroll
    for (int j = 0; j < 4; ++j) {
        int c = c0 + j * 8;
        op[r0 * 64 + c]           = acc[j][0];
        op[r0 * 64 + c + 1]       = acc[j][1];
        op[(r0 + 8) * 64 + c]     = acc[j][2];
        op[(r0 + 8) * 64 + c + 1] = acc[j][3];
    }
}

// ---------------------------------------------------------------------------
// M[n][c][h*64+k] = sum_v Wr[c][h*64+v] * ctx[n][h][k][v]  (bf16 out)
// ctx partial reduction + 1/rowsum fused here (ctxp is L2-resident).
// ---------------------------------------------------------------------------
__global__ void __launch_bounds__(256) k_M(const float* __restrict__ Wr)
{
    int ct = blockIdx.x, h = blockIdx.y, n = blockIdx.z;
    __shared__ float Ws[64][65];
    __shared__ float Cs[64][65];
    int t = threadIdx.x;
    int nh = n * 8 + h;

    for (int e = t; e < 4096; e += 256) {
        int r = e >> 6, c = e & 63;
        Ws[r][c] = Wr[(size_t)(ct * 64 + r) * 512 + h * 64 + c];
        float sum = 0.f;
#pragma unroll
        for (int ch = 0; ch < 8; ++ch)
            sum += g_ctxp[(size_t)(nh * 8 + ch) * 4096 + e];
        Cs[r][c] = sum / g_rows[nh * 64 + r];
    }
    __syncthreads();

    int c0 = (t >> 4) << 2;
    int k0 = (t & 15) << 2;
    float acc[4][4] = {};
    for (int v = 0; v < 64; ++v) {
        float a_[4], b_[4];
#pragma unroll
        for (int i = 0; i < 4; ++i) a_[i] = Ws[c0 + i][v];
#pragma unroll
        for (int j = 0; j < 4; ++j) b_[j] = Cs[k0 + j][v];
#pragma unroll
        for (int i = 0; i < 4; ++i)
#pragma unroll
            for (int j = 0; j < 4; ++j)
                acc[i][j] = fmaf(a_[i], b_[j], acc[i][j]);
    }
#pragma unroll
    for (int i = 0; i < 4; ++i)
#pragma unroll
        for (int j = 0; j < 4; ++j)
            g_Mb[(size_t)n * 262144 + (size_t)(ct * 64 + c0 + i) * 512 + h * 64 + k0 + j]
                = __float2bfloat16(acc[i][j]);
}

// ---------------------------------------------------------------------------
extern "C" void kernel_launch(void* const* d_in, const int* in_sizes, int n_in,
                              void* d_out, int out_size)
{
    const float* x  = (const float*)d_in[0];
    const float* Wk = (const float*)d_in[1];
    const float* bk = (const float*)d_in[2];
    const float* Wq = (const float*)d_in[3];
    const float* bq = (const float*)d_in[4];
    const float* Wv = (const float*)d_in[5];
    const float* bv = (const float*)d_in[6];
    const float* Wr = (const float*)d_in[7];
    const float* br = (const float*)d_in[8];
    float* out = (float*)d_out;

    bf16* wb;
    cudaGetSymbolAddress((void**)&wb, g_wb);

    cudaFuncSetAttribute(k_proj, cudaFuncAttributeMaxDynamicSharedMemorySize, SMEMSZ);
    cudaFuncSetAttribute(k_out,  cudaFuncAttributeMaxDynamicSharedMemorySize, SMEMSZ);

    k_convw_all<<<768, 256>>>(Wk, Wq, Wv, wb);
    k_convx<<<dim3(128, 8, 8), 256>>>(x);
    k_proj<<<dim3(64, 6, 8), 512, SMEMSZ>>>(bk, bq, bv);
    k_ctx<<<dim3(64, 8), 256>>>();
    k_M<<<dim3(8, 8, 8), 256>>>(Wr);
    k_out<<<dim3(64, 2, 8), 512, SMEMSZ>>>(x, br, out);
}